// round 2
// baseline (speedup 1.0000x reference)
#include <cuda_runtime.h>
#include <cstdint>
#include <cstddef>

// ============================================================================
// S6 kernel, algebraically reduced:
//   y[t,d] = x[t,d] * softplus((x@W1^T)[t,d] + b1[d]) * s[t]
//   s[t]   = sum_n (x@W2^T + b2)[t,n] * (x@W3^T + b3)[t,n]
// (h0 == 0 kills the exp(dA) term exactly.)
// Shapes: T = B*L = 4096 tokens, d = 1024, n = 16.
// ============================================================================

#define MAX_T 4096

__device__ float g_s[MAX_T];

// ---------------------------------------------------------------------------
// helpers
// ---------------------------------------------------------------------------
__device__ __forceinline__ uint32_t f2tf32(float f) {
    uint32_t r;
    asm("cvt.rna.tf32.f32 %0, %1;" : "=r"(r) : "f"(f));
    return r;
}

__device__ __forceinline__ float softplus_f(float z) {
    // matches jax.nn.softplus = logaddexp(z, 0) = max(z,0) + log1p(exp(-|z|))
    return fmaxf(z, 0.0f) + log1pf(expf(-fabsf(z)));
}

__device__ __forceinline__ void mma_tf32(float& c0, float& c1, float& c2, float& c3,
                                         uint32_t a0, uint32_t a1, uint32_t a2, uint32_t a3,
                                         uint32_t b0, uint32_t b1) {
    asm volatile(
        "mma.sync.aligned.m16n8k8.row.col.f32.tf32.tf32.f32 "
        "{%0,%1,%2,%3}, {%4,%5,%6,%7}, {%8,%9}, {%0,%1,%2,%3};\n"
        : "+f"(c0), "+f"(c1), "+f"(c2), "+f"(c3)
        : "r"(a0), "r"(a1), "r"(a2), "r"(a3), "r"(b0), "r"(b1));
}

// ---------------------------------------------------------------------------
// Kernel 1: per-token scalar s[t]
//   block = 256 threads, 32 tokens, 32 output cols (cols 0..15 from W2 -> B,
//   cols 16..31 from W3 -> C). K chunks of 64 through shared memory.
// ---------------------------------------------------------------------------
__global__ __launch_bounds__(256) void s_kernel(
    const float* __restrict__ x,
    const float* __restrict__ W2, const float* __restrict__ b2,
    const float* __restrict__ W3, const float* __restrict__ b3,
    int T, int d, int nst)
{
    const int LDX = 68;  // float stride; 68*4 bytes keeps float4 alignment
    __shared__ float xs[32 * 68];
    __shared__ float ws[32 * 68];
    __shared__ float outs[32 * 32];

    int tid = threadIdx.x;
    int t0  = blockIdx.x * 32;
    int tok = tid >> 3;          // 0..31
    int n0  = (tid & 7) * 4;     // 0..28

    float acc[4] = {0.f, 0.f, 0.f, 0.f};

    for (int k0 = 0; k0 < d; k0 += 64) {
        // load x tile: 32 tokens x 64 k
        #pragma unroll
        for (int it = 0; it < 2; it++) {
            int v  = tid + it * 256;
            int r  = v >> 4;
            int c4 = (v & 15) * 4;
            float4 val = *(const float4*)&x[(size_t)(t0 + r) * d + k0 + c4];
            *(float4*)&xs[r * LDX + c4] = val;
        }
        // load weight tile: rows 0..15 <- W2, rows 16..31 <- W3   (nst == 16)
        #pragma unroll
        for (int it = 0; it < 2; it++) {
            int v  = tid + it * 256;
            int r  = v >> 4;
            int c4 = (v & 15) * 4;
            const float* Wsrc = (r < 16) ? &W2[(size_t)r * d]
                                         : &W3[(size_t)(r - 16) * d];
            float4 val = *(const float4*)&Wsrc[k0 + c4];
            *(float4*)&ws[r * LDX + c4] = val;
        }
        __syncthreads();

        #pragma unroll
        for (int kk = 0; kk < 64; kk += 4) {
            float4 xv = *(const float4*)&xs[tok * LDX + kk];
            #pragma unroll
            for (int j = 0; j < 4; j++) {
                float4 wv = *(const float4*)&ws[(n0 + j) * LDX + kk];
                acc[j] += xv.x * wv.x + xv.y * wv.y + xv.z * wv.z + xv.w * wv.w;
            }
        }
        __syncthreads();
    }

    #pragma unroll
    for (int j = 0; j < 4; j++)
        outs[tok * 32 + n0 + j] = acc[j];
    __syncthreads();

    if (tid < 32) {
        int t = t0 + tid;
        if (t < T) {
            float s = 0.f;
            for (int n = 0; n < nst; n++) {
                float Bv = outs[tid * 32 + n]       + b2[n];
                float Cv = outs[tid * 32 + 16 + n]  + b3[n];
                s += Bv * Cv;
            }
            g_s[t] = s;
        }
    }
}

// ---------------------------------------------------------------------------
// Kernel 2: fused TF32 GEMM + epilogue
//   Z = X @ W1^T   (M=T=4096, N=d=1024, K=d=1024)
//   y = x * softplus(Z + b1) * s
// Tile: BM=128, BN=128, BK=32. 256 threads = 8 warps in 2x4 grid,
// warp tile 64(m) x 32(n) via m16n8k8 tf32 mma.sync.
// Smem stride 36 floats -> conflict-free fragment loads.
// ---------------------------------------------------------------------------
#define BM 128
#define BN 128
#define BK 32
#define LDA 36

__global__ __launch_bounds__(256) void main_kernel(
    const float* __restrict__ x,
    const float* __restrict__ W1,
    const float* __restrict__ b1,
    float* __restrict__ y,
    int T, int d)
{
    __shared__ float As[BM * LDA];
    __shared__ float Bs[BN * LDA];

    int tid  = threadIdx.x;
    int lane = tid & 31;
    int warp = tid >> 5;
    int wm   = warp >> 2;        // 0..1
    int wn   = warp & 3;         // 0..3
    int gid  = lane >> 2;        // 0..7
    int tig  = lane & 3;         // 0..3

    int bm = blockIdx.x * BM;    // token tile base
    int bn = blockIdx.y * BN;    // output-col tile base

    float acc[4][4][4];
    #pragma unroll
    for (int mi = 0; mi < 4; mi++)
        #pragma unroll
        for (int ni = 0; ni < 4; ni++)
            #pragma unroll
            for (int q = 0; q < 4; q++)
                acc[mi][ni][q] = 0.f;

    float4 ra[4], rb[4];

    // prefetch first tile into registers
    {
        #pragma unroll
        for (int i = 0; i < 4; i++) {
            int v  = tid + 256 * i;      // 0..1023 float4 slots
            int r  = v >> 3;             // 0..127
            int c4 = (v & 7) * 4;        // 0..28
            ra[i] = *(const float4*)&x [(size_t)(bm + r) * d + c4];
            rb[i] = *(const float4*)&W1[(size_t)(bn + r) * d + c4];
        }
    }

    for (int k0 = 0; k0 < d; k0 += BK) {
        __syncthreads();   // previous compute done before overwriting smem

        // store (converted to tf32) into smem
        #pragma unroll
        for (int i = 0; i < 4; i++) {
            int v  = tid + 256 * i;
            int r  = v >> 3;
            int c4 = (v & 7) * 4;
            float* pa = &As[r * LDA + c4];
            pa[0] = __uint_as_float(f2tf32(ra[i].x));
            pa[1] = __uint_as_float(f2tf32(ra[i].y));
            pa[2] = __uint_as_float(f2tf32(ra[i].z));
            pa[3] = __uint_as_float(f2tf32(ra[i].w));
            float* pb = &Bs[r * LDA + c4];
            pb[0] = __uint_as_float(f2tf32(rb[i].x));
            pb[1] = __uint_as_float(f2tf32(rb[i].y));
            pb[2] = __uint_as_float(f2tf32(rb[i].z));
            pb[3] = __uint_as_float(f2tf32(rb[i].w));
        }
        __syncthreads();

        // prefetch next tile (overlaps with the mma work below)
        if (k0 + BK < d) {
            #pragma unroll
            for (int i = 0; i < 4; i++) {
                int v  = tid + 256 * i;
                int r  = v >> 3;
                int c4 = (v & 7) * 4;
                ra[i] = *(const float4*)&x [(size_t)(bm + r) * d + k0 + BK + c4];
                rb[i] = *(const float4*)&W1[(size_t)(bn + r) * d + k0 + BK + c4];
            }
        }

        // compute: 4 k8-steps over this BK=32 slab
        #pragma unroll
        for (int kk = 0; kk < BK; kk += 8) {
            uint32_t afr[4][4];
            uint32_t bfr[4][2];
            #pragma unroll
            for (int mi = 0; mi < 4; mi++) {
                int r = wm * 64 + mi * 16 + gid;
                const float* p = &As[r * LDA + kk + tig];
                afr[mi][0] = __float_as_uint(p[0]);
                afr[mi][1] = __float_as_uint(p[8 * LDA]);
                afr[mi][2] = __float_as_uint(p[4]);
                afr[mi][3] = __float_as_uint(p[8 * LDA + 4]);
            }
            #pragma unroll
            for (int ni = 0; ni < 4; ni++) {
                int n = wn * 32 + ni * 8 + gid;
                const float* p = &Bs[n * LDA + kk + tig];
                bfr[ni][0] = __float_as_uint(p[0]);
                bfr[ni][1] = __float_as_uint(p[4]);
            }
            #pragma unroll
            for (int mi = 0; mi < 4; mi++)
                #pragma unroll
                for (int ni = 0; ni < 4; ni++)
                    mma_tf32(acc[mi][ni][0], acc[mi][ni][1],
                             acc[mi][ni][2], acc[mi][ni][3],
                             afr[mi][0], afr[mi][1], afr[mi][2], afr[mi][3],
                             bfr[ni][0], bfr[ni][1]);
        }
    }

    // fused epilogue: y = x * softplus(z + b1) * s
    #pragma unroll
    for (int mi = 0; mi < 4; mi++) {
        int r0 = bm + wm * 64 + mi * 16 + gid;
        int r1 = r0 + 8;
        float sv0 = g_s[r0];
        float sv1 = g_s[r1];
        #pragma unroll
        for (int ni = 0; ni < 4; ni++) {
            int c0 = bn + wn * 32 + ni * 8 + tig * 2;
            int c1 = c0 + 1;
            float bias0 = b1[c0];
            float bias1 = b1[c1];

            float sp;
            sp = softplus_f(acc[mi][ni][0] + bias0);
            y[(size_t)r0 * d + c0] = x[(size_t)r0 * d + c0] * sp * sv0;
            sp = softplus_f(acc[mi][ni][1] + bias1);
            y[(size_t)r0 * d + c1] = x[(size_t)r0 * d + c1] * sp * sv0;
            sp = softplus_f(acc[mi][ni][2] + bias0);
            y[(size_t)r1 * d + c0] = x[(size_t)r1 * d + c0] * sp * sv1;
            sp = softplus_f(acc[mi][ni][3] + bias1);
            y[(size_t)r1 * d + c1] = x[(size_t)r1 * d + c1] * sp * sv1;
        }
    }
}

// ---------------------------------------------------------------------------
// launch
// inputs (metadata order): x, W1, b1, W2, b2, W3, b3, A
// ---------------------------------------------------------------------------
extern "C" void kernel_launch(void* const* d_in, const int* in_sizes, int n_in,
                              void* d_out, int out_size)
{
    const float* x  = (const float*)d_in[0];
    const float* W1 = (const float*)d_in[1];
    const float* b1 = (const float*)d_in[2];
    const float* W2 = (const float*)d_in[3];
    const float* b2 = (const float*)d_in[4];
    const float* W3 = (const float*)d_in[5];
    const float* b3 = (const float*)d_in[6];
    // d_in[7] = A: mathematically unused (h0 == 0 kills the exp(dA)*h0 term)

    int d   = in_sizes[2];          // b1 length = d_model (1024)
    int nst = in_sizes[4];          // b2 length = state size (16)
    int T   = in_sizes[0] / d;      // tokens = B*L (4096)

    float* y = (float*)d_out;

    s_kernel<<<T / 32, 256>>>(x, W2, b2, W3, b3, T, d, nst);

    dim3 grid(T / BM, d / BN);
    main_kernel<<<grid, 256>>>(x, W1, b1, y, T, d);
}

// round 4
// speedup vs baseline: 1.0758x; 1.0758x over previous
#include <cuda_runtime.h>
#include <cstdint>
#include <cstddef>

// ============================================================================
// S6 kernel, algebraically reduced:
//   y[t,d] = x[t,d] * softplus((x@W1^T)[t,d] + b1[d]) * s[t]
//   s[t]   = sum_n (x@W2^T + b2)[t,n] * (x@W3^T + b3)[t,n]
// (h0 == 0 kills the exp(dA) term exactly; input A is mathematically unused.)
// Shapes: T = B*L = 4096 tokens, d = 1024, n = 16.
// ============================================================================

#define MAX_T 4096
__device__ float g_s[MAX_T];

// ---------------------------------------------------------------------------
// helpers
// ---------------------------------------------------------------------------
__device__ __forceinline__ float tf32r(float f) {
    uint32_t r;
    asm("cvt.rna.tf32.f32 %0, %1;" : "=r"(r) : "f"(f));
    return __uint_as_float(r);
}

__device__ __forceinline__ float softplus_f(float z) {
    return fmaxf(z, 0.0f) + log1pf(expf(-fabsf(z)));
}

__device__ __forceinline__ void mma_tf32(float& c0, float& c1, float& c2, float& c3,
                                         float a0, float a1, float a2, float a3,
                                         float b0, float b1) {
    asm volatile(
        "mma.sync.aligned.m16n8k8.row.col.f32.tf32.tf32.f32 "
        "{%0,%1,%2,%3}, {%4,%5,%6,%7}, {%8,%9}, {%0,%1,%2,%3};\n"
        : "+f"(c0), "+f"(c1), "+f"(c2), "+f"(c3)
        : "r"(__float_as_uint(a0)), "r"(__float_as_uint(a1)),
          "r"(__float_as_uint(a2)), "r"(__float_as_uint(a3)),
          "r"(__float_as_uint(b0)), "r"(__float_as_uint(b1)));
}

__device__ __forceinline__ void cp16(uint32_t dst_smem, const void* src) {
    asm volatile("cp.async.cg.shared.global [%0], [%1], 16;"
                 :: "r"(dst_smem), "l"(src));
}
__device__ __forceinline__ void cp_commit() {
    asm volatile("cp.async.commit_group;");
}
__device__ __forceinline__ void cp_wait0() {
    asm volatile("cp.async.wait_group 0;" ::: "memory");
}

#define LDA 36   // float stride: conflict-free frags, 144B rows keep 16B align

// ---------------------------------------------------------------------------
// Kernel 1: s[t] via tensor cores.
//   Z2 = X @ [W2;W3]^T  (M-tile 64, N=32, K=d), then s from the accumulator
//   layout directly (cols n and n+16 land on the SAME thread), 2x shfl.bfly.
//   4 warps, each warp: 16 rows x 32 cols. grid = T/64.
// ---------------------------------------------------------------------------
__global__ __launch_bounds__(128) void s_kernel(
    const float* __restrict__ x,
    const float* __restrict__ W2, const float* __restrict__ b2,
    const float* __restrict__ W3, const float* __restrict__ b3,
    int T, int d)
{
    __shared__ float Xs[64 * LDA];
    __shared__ float Ws[32 * LDA];

    int tid  = threadIdx.x;
    int lane = tid & 31;
    int w    = tid >> 5;         // 0..3 -> 16-row group
    int gid  = lane >> 2;
    int tig  = lane & 3;

    int t0 = blockIdx.x * 64;

    uint32_t sX = (uint32_t)__cvta_generic_to_shared(Xs);
    uint32_t sW = (uint32_t)__cvta_generic_to_shared(Ws);

    int rbase = tid >> 3;          // 0..15
    int c4    = (tid & 7) * 4;     // 0..28
    const float* xptr  = x  + (size_t)(t0 + rbase) * d + c4;
    const float* wptr0 = W2 + (size_t)rbase * d + c4;  // rows 0..15
    const float* wptr1 = W3 + (size_t)rbase * d + c4;  // rows 16..31

    float acc[4][4];
    #pragma unroll
    for (int i = 0; i < 4; i++)
        #pragma unroll
        for (int q = 0; q < 4; q++) acc[i][q] = 0.f;

    for (int k0 = 0; k0 < d; k0 += 32) {
        // X tile: 64 x 32
        #pragma unroll
        for (int i = 0; i < 4; i++)
            cp16(sX + (uint32_t)(((rbase + 16 * i) * LDA + c4) * 4),
                 xptr + (size_t)(16 * i) * d + k0);
        // W tile: rows 0..15 = W2, 16..31 = W3
        cp16(sW + (uint32_t)((rbase * LDA + c4) * 4),        wptr0 + k0);
        cp16(sW + (uint32_t)(((rbase + 16) * LDA + c4) * 4), wptr1 + k0);
        cp_commit();
        cp_wait0();
        __syncthreads();

        #pragma unroll
        for (int kk = 0; kk < 32; kk += 8) {
            int r = w * 16 + gid;
            const float* pa = &Xs[r * LDA + kk + tig];
            float a0 = tf32r(pa[0]);
            float a1 = tf32r(pa[8 * LDA]);
            float a2 = tf32r(pa[4]);
            float a3 = tf32r(pa[8 * LDA + 4]);
            #pragma unroll
            for (int ni = 0; ni < 4; ni++) {
                const float* pb = &Ws[(ni * 8 + gid) * LDA + kk + tig];
                float b0 = tf32r(pb[0]);
                float b1 = tf32r(pb[4]);
                mma_tf32(acc[ni][0], acc[ni][1], acc[ni][2], acc[ni][3],
                         a0, a1, a2, a3, b0, b1);
            }
        }
        __syncthreads();
    }

    // epilogue: s = sum_n (Z[:,n]+b2[n]) * (Z[:,n+16]+b3[n])
    // col(n) = ni*8 + tig*2 + j ; pair (n, n+16) lives in (ni, ni+2), same lane
    int nb0 = tig * 2, nb1 = nb0 + 1, nb2 = nb0 + 8, nb3 = nb0 + 9;
    float p2[4] = {b2[nb0], b2[nb1], b2[nb2], b2[nb3]};
    float p3[4] = {b3[nb0], b3[nb1], b3[nb2], b3[nb3]};

    #pragma unroll
    for (int h = 0; h < 2; h++) {
        float p =
            (acc[0][h*2+0] + p2[0]) * (acc[2][h*2+0] + p3[0]) +
            (acc[0][h*2+1] + p2[1]) * (acc[2][h*2+1] + p3[1]) +
            (acc[1][h*2+0] + p2[2]) * (acc[3][h*2+0] + p3[2]) +
            (acc[1][h*2+1] + p2[3]) * (acc[3][h*2+1] + p3[3]);
        p += __shfl_xor_sync(0xffffffffu, p, 1);
        p += __shfl_xor_sync(0xffffffffu, p, 2);
        if (tig == 0) {
            int t = t0 + w * 16 + gid + h * 8;
            if (t < T) g_s[t] = p;
        }
    }
}

// ---------------------------------------------------------------------------
// Kernel 2: fused TF32 GEMM + epilogue.
//   Z = X @ W1^T, y = x * softplus(Z + b1) * s
// BM=BN=128, BK=32. 128 threads = 4 warps (2x2), warp tile 64x64.
// cp.async gmem->smem, tf32 cvt on fragment registers.
// ---------------------------------------------------------------------------
__global__ __launch_bounds__(128) void main_kernel(
    const float* __restrict__ x,
    const float* __restrict__ W1,
    const float* __restrict__ b1,
    float* __restrict__ y,
    int T, int d)
{
    __shared__ float As[128 * LDA];
    __shared__ float Bs[128 * LDA];

    int tid  = threadIdx.x;
    int lane = tid & 31;
    int warp = tid >> 5;
    int wm   = warp >> 1;        // 0..1
    int wn   = warp & 1;         // 0..1
    int gid  = lane >> 2;        // 0..7
    int tig  = lane & 3;         // 0..3

    int bm = blockIdx.x * 128;
    int bn = blockIdx.y * 128;

    uint32_t sA = (uint32_t)__cvta_generic_to_shared(As);
    uint32_t sB = (uint32_t)__cvta_generic_to_shared(Bs);

    int rbase = tid >> 3;          // 0..15
    int c4    = (tid & 7) * 4;     // 0..28
    const float* aptr = x  + (size_t)(bm + rbase) * d + c4;
    const float* bptr = W1 + (size_t)(bn + rbase) * d + c4;

    float acc[4][8][4];
    #pragma unroll
    for (int mi = 0; mi < 4; mi++)
        #pragma unroll
        for (int ni = 0; ni < 8; ni++)
            #pragma unroll
            for (int q = 0; q < 4; q++) acc[mi][ni][q] = 0.f;

    for (int k0 = 0; k0 < d; k0 += 32) {
        #pragma unroll
        for (int i = 0; i < 8; i++) {
            uint32_t doff = (uint32_t)(((rbase + 16 * i) * LDA + c4) * 4);
            size_t   goff = (size_t)(16 * i) * d + k0;
            cp16(sA + doff, aptr + goff);
            cp16(sB + doff, bptr + goff);
        }
        cp_commit();
        cp_wait0();
        __syncthreads();

        #pragma unroll
        for (int kk = 0; kk < 32; kk += 8) {
            float afr[4][4];
            float bfr[8][2];
            #pragma unroll
            for (int mi = 0; mi < 4; mi++) {
                int r = wm * 64 + mi * 16 + gid;
                const float* p = &As[r * LDA + kk + tig];
                afr[mi][0] = tf32r(p[0]);
                afr[mi][1] = tf32r(p[8 * LDA]);
                afr[mi][2] = tf32r(p[4]);
                afr[mi][3] = tf32r(p[8 * LDA + 4]);
            }
            #pragma unroll
            for (int ni = 0; ni < 8; ni++) {
                int n = wn * 64 + ni * 8 + gid;
                const float* p = &Bs[n * LDA + kk + tig];
                bfr[ni][0] = tf32r(p[0]);
                bfr[ni][1] = tf32r(p[4]);
            }
            #pragma unroll
            for (int mi = 0; mi < 4; mi++)
                #pragma unroll
                for (int ni = 0; ni < 8; ni++)
                    mma_tf32(acc[mi][ni][0], acc[mi][ni][1],
                             acc[mi][ni][2], acc[mi][ni][3],
                             afr[mi][0], afr[mi][1], afr[mi][2], afr[mi][3],
                             bfr[ni][0], bfr[ni][1]);
        }
        __syncthreads();
    }

    // fused epilogue: y = x * softplus(z + b1) * s
    #pragma unroll
    for (int mi = 0; mi < 4; mi++) {
        int r0 = bm + wm * 64 + mi * 16 + gid;
        int r1 = r0 + 8;
        float sv0 = g_s[r0];
        float sv1 = g_s[r1];
        #pragma unroll
        for (int ni = 0; ni < 8; ni++) {
            int c0 = bn + wn * 64 + ni * 8 + tig * 2;
            float2 bias = *(const float2*)&b1[c0];

            float2 x0 = *(const float2*)&x[(size_t)r0 * d + c0];
            float2 x1 = *(const float2*)&x[(size_t)r1 * d + c0];

            float2 o0, o1;
            o0.x = x0.x * softplus_f(acc[mi][ni][0] + bias.x) * sv0;
            o0.y = x0.y * softplus_f(acc[mi][ni][1] + bias.y) * sv0;
            o1.x = x1.x * softplus_f(acc[mi][ni][2] + bias.x) * sv1;
            o1.y = x1.y * softplus_f(acc[mi][ni][3] + bias.y) * sv1;

            *(float2*)&y[(size_t)r0 * d + c0] = o0;
            *(float2*)&y[(size_t)r1 * d + c0] = o1;
        }
    }
}

// ---------------------------------------------------------------------------
// launch — inputs (metadata order): x, W1, b1, W2, b2, W3, b3, A
// ---------------------------------------------------------------------------
extern "C" void kernel_launch(void* const* d_in, const int* in_sizes, int n_in,
                              void* d_out, int out_size)
{
    const float* x  = (const float*)d_in[0];
    const float* W1 = (const float*)d_in[1];
    const float* b1 = (const float*)d_in[2];
    const float* W2 = (const float*)d_in[3];
    const float* b2 = (const float*)d_in[4];
    const float* W3 = (const float*)d_in[5];
    const float* b3 = (const float*)d_in[6];
    // d_in[7] = A: unused (h0 == 0 kills exp(dA)*h0 exactly)

    int d = in_sizes[2];          // b1 length = d_model (1024)
    int T = in_sizes[0] / d;      // tokens = B*L (4096)

    float* y = (float*)d_out;

    s_kernel<<<T / 64, 128>>>(x, W2, b2, W3, b3, T, d);

    dim3 grid(T / 128, d / 128);
    main_kernel<<<grid, 128>>>(x, W1, b1, y, T, d);
}

// round 7
// speedup vs baseline: 2.1455x; 1.9943x over previous
#include <cuda_runtime.h>
#include <cstdint>
#include <cstddef>

// ============================================================================
// S6 reduced:  y[t,d] = x[t,d] * softplus((x@W1^T)[t,d] + b1[d]) * s[t]
//              s[t]   = sum_n (x@W2^T+b2)[t,n] * (x@W3^T+b3)[t,n]
// (h0 == 0 kills the exp(dA) term exactly; A unused.)
// T=4096, d=1024, n=16.  mma.sync tf32 (sm_103 non-'a' target: no tcgen05).
// ============================================================================

#define MAX_T 4096
__device__ float g_s[MAX_T];

// ---------------------------------------------------------------------------
// helpers
// ---------------------------------------------------------------------------
__device__ __forceinline__ float tf32r(float f) {
    uint32_t r; asm("cvt.rna.tf32.f32 %0, %1;" : "=r"(r) : "f"(f));
    return __uint_as_float(r);
}
__device__ __forceinline__ float softplus_f(float z) {
    return fmaxf(z, 0.0f) + log1pf(expf(-fabsf(z)));
}
__device__ __forceinline__ void mma_tf32(float& c0, float& c1, float& c2, float& c3,
                                         float a0, float a1, float a2, float a3,
                                         float b0, float b1) {
    asm volatile(
        "mma.sync.aligned.m16n8k8.row.col.f32.tf32.tf32.f32 "
        "{%0,%1,%2,%3}, {%4,%5,%6,%7}, {%8,%9}, {%0,%1,%2,%3};\n"
        : "+f"(c0), "+f"(c1), "+f"(c2), "+f"(c3)
        : "r"(__float_as_uint(a0)), "r"(__float_as_uint(a1)),
          "r"(__float_as_uint(a2)), "r"(__float_as_uint(a3)),
          "r"(__float_as_uint(b0)), "r"(__float_as_uint(b1)));
}
__device__ __forceinline__ void cp16(uint32_t dst_smem, const void* src) {
    asm volatile("cp.async.cg.shared.global [%0], [%1], 16;"
                 :: "r"(dst_smem), "l"(src));
}
__device__ __forceinline__ void cp_commit() {
    asm volatile("cp.async.commit_group;");
}
template <int N>
__device__ __forceinline__ void cp_wait() {
    asm volatile("cp.async.wait_group %0;" :: "n"(N) : "memory");
}

// ---------------------------------------------------------------------------
// main_kernel: Z = X @ W1^T, y = x * softplus(Z+b1) * s
// BM=BN=128, BK=32.  128 threads = 4 warps (2x2), warp tile 64x64.
// XOR-swizzled smem tiles (128 rows x 32 floats, no padding), 3-stage
// cp.async pipeline, 2 CTAs/SM.  grid = (T/128, d/128) = (32, 8) = 256 CTAs.
// ---------------------------------------------------------------------------
#define MS 3                       // pipeline stages
#define MSTG 32768                 // bytes per stage (A 16KB + B 16KB)

__global__ __launch_bounds__(128, 2) void main_kernel(
    const float* __restrict__ x, const float* __restrict__ W1,
    const float* __restrict__ b1, float* __restrict__ y, int T, int d)
{
    extern __shared__ float smem[];
    uint32_t sbase = (uint32_t)__cvta_generic_to_shared(smem);

    int tid  = threadIdx.x;
    int lane = tid & 31;
    int warp = tid >> 5;
    int wm   = warp >> 1;        // 0..1
    int wn   = warp & 1;         // 0..1
    int gid  = lane >> 2;        // 0..7
    int tig  = lane & 3;         // 0..3

    int bm = blockIdx.x * 128;
    int bn = blockIdx.y * 128;

    // gmem->smem geometry: thread handles 8 rows (lrow + 16j), one float4 each
    int lrow = tid >> 3;          // 0..15
    int lc4  = (tid & 7) * 4;     // 0..28
    uint32_t soff[8];             // swizzled byte offsets (identical for A & B)
    #pragma unroll
    for (int j = 0; j < 8; j++) {
        int r = lrow + 16 * j;
        soff[j] = (uint32_t)((r * 32 + (lc4 ^ ((r & 7) << 2))) * 4);
    }
    const float* aptr = x  + (size_t)(bm + lrow) * d + lc4;
    const float* bptr = W1 + (size_t)(bn + lrow) * d + lc4;

    float acc[4][8][4];
    #pragma unroll
    for (int mi = 0; mi < 4; mi++)
        #pragma unroll
        for (int ni = 0; ni < 8; ni++)
            #pragma unroll
            for (int q = 0; q < 4; q++) acc[mi][ni][q] = 0.f;

    const int nslab = d / 32;     // 32

    // ---- pipeline prologue: issue stages 0..MS-2 ----
    #pragma unroll
    for (int j = 0; j < MS - 1; j++) {
        uint32_t sa = sbase + (uint32_t)(j * MSTG);
        uint32_t sb = sa + 16384u;
        int k0 = j * 32;
        #pragma unroll
        for (int q = 0; q < 8; q++) {
            cp16(sa + soff[q], aptr + (size_t)(16 * q) * d + k0);
            cp16(sb + soff[q], bptr + (size_t)(16 * q) * d + k0);
        }
        cp_commit();
    }

    int xr = gid << 2;

    for (int i = 0; i < nslab; i++) {
        cp_wait<MS - 2>();        // slab i resident
        __syncthreads();

        // issue load for slab i+MS-1 into the stage freed by slab i-1
        int jn = i + MS - 1;
        if (jn < nslab) {
            uint32_t sa = sbase + (uint32_t)((jn % MS) * MSTG);
            uint32_t sb = sa + 16384u;
            int k0 = jn * 32;
            #pragma unroll
            for (int q = 0; q < 8; q++) {
                cp16(sa + soff[q], aptr + (size_t)(16 * q) * d + k0);
                cp16(sb + soff[q], bptr + (size_t)(16 * q) * d + k0);
            }
        }
        cp_commit();

        // compute slab i from stage i%MS
        const float* As = smem + (size_t)(i % MS) * (MSTG / 4);
        const float* Bs = As + 4096;

        #pragma unroll
        for (int kk = 0; kk < 32; kk += 8) {
            int c1 = (kk + tig) ^ xr;
            int c2 = (kk + tig + 4) ^ xr;
            float afr[4][4];
            float bfr[8][2];
            #pragma unroll
            for (int mi = 0; mi < 4; mi++) {
                int r = wm * 64 + mi * 16 + gid;
                afr[mi][0] = tf32r(As[r * 32 + c1]);
                afr[mi][1] = tf32r(As[(r + 8) * 32 + c1]);
                afr[mi][2] = tf32r(As[r * 32 + c2]);
                afr[mi][3] = tf32r(As[(r + 8) * 32 + c2]);
            }
            #pragma unroll
            for (int ni = 0; ni < 8; ni++) {
                int n = wn * 64 + ni * 8 + gid;
                bfr[ni][0] = tf32r(Bs[n * 32 + c1]);
                bfr[ni][1] = tf32r(Bs[n * 32 + c2]);
            }
            #pragma unroll
            for (int mi = 0; mi < 4; mi++)
                #pragma unroll
                for (int ni = 0; ni < 8; ni++)
                    mma_tf32(acc[mi][ni][0], acc[mi][ni][1],
                             acc[mi][ni][2], acc[mi][ni][3],
                             afr[mi][0], afr[mi][1], afr[mi][2], afr[mi][3],
                             bfr[ni][0], bfr[ni][1]);
        }
    }

    // ---- fused epilogue: y = x * softplus(z + b1) * s ----
    #pragma unroll
    for (int mi = 0; mi < 4; mi++) {
        int r0 = bm + wm * 64 + mi * 16 + gid;
        int r1 = r0 + 8;
        float sv0 = g_s[r0];
        float sv1 = g_s[r1];
        #pragma unroll
        for (int ni = 0; ni < 8; ni++) {
            int c0 = bn + wn * 64 + ni * 8 + tig * 2;
            float2 bias = *(const float2*)&b1[c0];
            float2 x0 = *(const float2*)&x[(size_t)r0 * d + c0];
            float2 x1 = *(const float2*)&x[(size_t)r1 * d + c0];
            float2 o0, o1;
            o0.x = x0.x * softplus_f(acc[mi][ni][0] + bias.x) * sv0;
            o0.y = x0.y * softplus_f(acc[mi][ni][1] + bias.y) * sv0;
            o1.x = x1.x * softplus_f(acc[mi][ni][2] + bias.x) * sv1;
            o1.y = x1.y * softplus_f(acc[mi][ni][3] + bias.y) * sv1;
            *(float2*)&y[(size_t)r0 * d + c0] = o0;
            *(float2*)&y[(size_t)r1 * d + c0] = o1;
        }
    }
}

// ---------------------------------------------------------------------------
// s_kernel: Z2 = X @ [W2;W3]^T  (64 tokens/CTA, N=32, K=d), tensor cores,
// 4-stage cp.async pipeline.  s from the m16n8 accumulator layout:
// pair (n, n+16) lands on the same lane; 2x shfl.bfly reduce.  grid = T/64.
// ---------------------------------------------------------------------------
#define SS 4                        // stages
#define SSTG 12288                  // bytes/stage: A 64x32 (8KB) + B 32x32 (4KB)

__global__ __launch_bounds__(128, 2) void s_kernel(
    const float* __restrict__ x,
    const float* __restrict__ W2, const float* __restrict__ b2,
    const float* __restrict__ W3, const float* __restrict__ b3,
    int T, int d)
{
    extern __shared__ float smem[];
    uint32_t sbase = (uint32_t)__cvta_generic_to_shared(smem);

    int tid  = threadIdx.x;
    int lane = tid & 31;
    int w    = tid >> 5;          // warp 0..3 -> 16-token group
    int gid  = lane >> 2;
    int tig  = lane & 3;
    int t0   = blockIdx.x * 64;

    int lrow = tid >> 3;          // 0..15
    int lc4  = (tid & 7) * 4;
    uint32_t aoff[4], boff[2];
    #pragma unroll
    for (int j = 0; j < 4; j++) {
        int r = lrow + 16 * j;
        aoff[j] = (uint32_t)((r * 32 + (lc4 ^ ((r & 7) << 2))) * 4);
    }
    #pragma unroll
    for (int j = 0; j < 2; j++) {
        int r = lrow + 16 * j;
        boff[j] = (uint32_t)((r * 32 + (lc4 ^ ((r & 7) << 2))) * 4);
    }
    const float* xptr  = x  + (size_t)(t0 + lrow) * d + lc4;
    const float* wptr0 = W2 + (size_t)lrow * d + lc4;   // B rows  0..15
    const float* wptr1 = W3 + (size_t)lrow * d + lc4;   // B rows 16..31

    float acc[4][4];
    #pragma unroll
    for (int i = 0; i < 4; i++)
        #pragma unroll
        for (int q = 0; q < 4; q++) acc[i][q] = 0.f;

    const int nslab = d / 32;

    #pragma unroll
    for (int j = 0; j < SS - 1; j++) {
        uint32_t sa = sbase + (uint32_t)(j * SSTG);
        uint32_t sb = sa + 8192u;
        int k0 = j * 32;
        #pragma unroll
        for (int q = 0; q < 4; q++)
            cp16(sa + aoff[q], xptr + (size_t)(16 * q) * d + k0);
        cp16(sb + boff[0], wptr0 + k0);
        cp16(sb + boff[1], wptr1 + k0);
        cp_commit();
    }

    int xr = gid << 2;

    for (int i = 0; i < nslab; i++) {
        cp_wait<SS - 2>();
        __syncthreads();

        int jn = i + SS - 1;
        if (jn < nslab) {
            uint32_t sa = sbase + (uint32_t)((jn % SS) * SSTG);
            uint32_t sb = sa + 8192u;
            int k0 = jn * 32;
            #pragma unroll
            for (int q = 0; q < 4; q++)
                cp16(sa + aoff[q], xptr + (size_t)(16 * q) * d + k0);
            cp16(sb + boff[0], wptr0 + k0);
            cp16(sb + boff[1], wptr1 + k0);
        }
        cp_commit();

        const float* As = smem + (size_t)(i % SS) * (SSTG / 4);
        const float* Bs = As + 2048;

        #pragma unroll
        for (int kk = 0; kk < 32; kk += 8) {
            int c1 = (kk + tig) ^ xr;
            int c2 = (kk + tig + 4) ^ xr;
            int r = w * 16 + gid;
            float a0 = tf32r(As[r * 32 + c1]);
            float a1 = tf32r(As[(r + 8) * 32 + c1]);
            float a2 = tf32r(As[r * 32 + c2]);
            float a3 = tf32r(As[(r + 8) * 32 + c2]);
            #pragma unroll
            for (int ni = 0; ni < 4; ni++) {
                int n = ni * 8 + gid;
                float b0 = tf32r(Bs[n * 32 + c1]);
                float b1v = tf32r(Bs[n * 32 + c2]);
                mma_tf32(acc[ni][0], acc[ni][1], acc[ni][2], acc[ni][3],
                         a0, a1, a2, a3, b0, b1v);
            }
        }
    }

    // s = sum_n (Z[:,n]+b2[n]) * (Z[:,n+16]+b3[n]);  col(n) = ni*8 + tig*2 + j
    int nb0 = tig * 2, nb1 = nb0 + 1, nb2 = nb0 + 8, nb3 = nb0 + 9;
    float p2[4] = {b2[nb0], b2[nb1], b2[nb2], b2[nb3]};
    float p3[4] = {b3[nb0], b3[nb1], b3[nb2], b3[nb3]};

    #pragma unroll
    for (int h = 0; h < 2; h++) {
        float p =
            (acc[0][h*2+0] + p2[0]) * (acc[2][h*2+0] + p3[0]) +
            (acc[0][h*2+1] + p2[1]) * (acc[2][h*2+1] + p3[1]) +
            (acc[1][h*2+0] + p2[2]) * (acc[3][h*2+0] + p3[2]) +
            (acc[1][h*2+1] + p2[3]) * (acc[3][h*2+1] + p3[3]);
        p += __shfl_xor_sync(0xffffffffu, p, 1);
        p += __shfl_xor_sync(0xffffffffu, p, 2);
        if (tig == 0) {
            int t = t0 + w * 16 + gid + h * 8;
            if (t < T) g_s[t] = p;
        }
    }
}

// ---------------------------------------------------------------------------
// launch — inputs (metadata order): x, W1, b1, W2, b2, W3, b3, A
// ---------------------------------------------------------------------------
extern "C" void kernel_launch(void* const* d_in, const int* in_sizes, int n_in,
                              void* d_out, int out_size)
{
    const float* x  = (const float*)d_in[0];
    const float* W1 = (const float*)d_in[1];
    const float* b1 = (const float*)d_in[2];
    const float* W2 = (const float*)d_in[3];
    const float* b2 = (const float*)d_in[4];
    const float* W3 = (const float*)d_in[5];
    const float* b3 = (const float*)d_in[6];
    // d_in[7] = A: unused (h0 == 0 kills exp(dA)*h0 exactly)

    int d = in_sizes[2];          // d_model (1024)
    int T = in_sizes[0] / d;      // tokens (4096)
    float* y = (float*)d_out;

    const int SMEM_MAIN = MS * MSTG;   // 3 * 32KB = 96KB
    const int SMEM_S    = SS * SSTG;   // 4 * 12KB = 48KB

    cudaFuncSetAttribute(main_kernel, cudaFuncAttributeMaxDynamicSharedMemorySize, SMEM_MAIN);
    cudaFuncSetAttribute(s_kernel,    cudaFuncAttributeMaxDynamicSharedMemorySize, SMEM_S);

    s_kernel<<<T / 64, 128, SMEM_S>>>(x, W2, b2, W3, b3, T, d);
    dim3 grid(T / 128, d / 128);
    main_kernel<<<grid, 128, SMEM_MAIN>>>(x, W1, b1, y, T, d);
}

// round 9
// speedup vs baseline: 3.1513x; 1.4688x over previous
#include <cuda_runtime.h>
#include <cuda_fp16.h>
#include <cstdint>
#include <cstddef>

// ============================================================================
// S6 reduced:  y[t,d] = x[t,d] * softplus((x@W1^T)[t,d] + b1[d]) * s[t]
//              s[t]   = sum_n (x@W2^T+b2)[t,n] * (x@W3^T+b3)[t,n]
// (h0 == 0 kills the exp(dA) term exactly; A unused.)
// T=4096, d=1024, n=16.
// Main GEMM: fp16 inputs (== tf32 precision: 11-bit mantissa) + fp32 accum,
// ldmatrix fragments, cp.async 4-stage pipeline.  Prepass converts x,W1 to
// fp16 scratch once.  s_kernel: tf32 mma (unchanged, known-good).
// ============================================================================

#define MAX_T   4096
#define D_MODEL 1024

__device__ float g_s[MAX_T];
__device__ __align__(16) __half g_xh [MAX_T * D_MODEL];
__device__ __align__(16) __half g_w1h[D_MODEL * D_MODEL];

// ---------------------------------------------------------------------------
// helpers
// ---------------------------------------------------------------------------
__device__ __forceinline__ float tf32r(float f) {
    uint32_t r; asm("cvt.rna.tf32.f32 %0, %1;" : "=r"(r) : "f"(f));
    return __uint_as_float(r);
}
__device__ __forceinline__ float softplus_f(float z) {
    return fmaxf(z, 0.0f) + log1pf(expf(-fabsf(z)));
}
__device__ __forceinline__ void mma_tf32(float& c0, float& c1, float& c2, float& c3,
                                         float a0, float a1, float a2, float a3,
                                         float b0, float b1) {
    asm volatile(
        "mma.sync.aligned.m16n8k8.row.col.f32.tf32.tf32.f32 "
        "{%0,%1,%2,%3}, {%4,%5,%6,%7}, {%8,%9}, {%0,%1,%2,%3};\n"
        : "+f"(c0), "+f"(c1), "+f"(c2), "+f"(c3)
        : "r"(__float_as_uint(a0)), "r"(__float_as_uint(a1)),
          "r"(__float_as_uint(a2)), "r"(__float_as_uint(a3)),
          "r"(__float_as_uint(b0)), "r"(__float_as_uint(b1)));
}
__device__ __forceinline__ void mma_f16(float& c0, float& c1, float& c2, float& c3,
                                        uint32_t a0, uint32_t a1, uint32_t a2, uint32_t a3,
                                        uint32_t b0, uint32_t b1) {
    asm volatile(
        "mma.sync.aligned.m16n8k16.row.col.f32.f16.f16.f32 "
        "{%0,%1,%2,%3}, {%4,%5,%6,%7}, {%8,%9}, {%0,%1,%2,%3};\n"
        : "+f"(c0), "+f"(c1), "+f"(c2), "+f"(c3)
        : "r"(a0), "r"(a1), "r"(a2), "r"(a3), "r"(b0), "r"(b1));
}
__device__ __forceinline__ void ldsm4(uint32_t* r, uint32_t addr) {
    asm volatile("ldmatrix.sync.aligned.m8n8.x4.shared.b16 {%0,%1,%2,%3}, [%4];"
                 : "=r"(r[0]), "=r"(r[1]), "=r"(r[2]), "=r"(r[3]) : "r"(addr));
}
__device__ __forceinline__ void cp16(uint32_t dst_smem, const void* src) {
    asm volatile("cp.async.cg.shared.global [%0], [%1], 16;"
                 :: "r"(dst_smem), "l"(src));
}
__device__ __forceinline__ void cp_commit() {
    asm volatile("cp.async.commit_group;");
}
template <int N>
__device__ __forceinline__ void cp_wait() {
    asm volatile("cp.async.wait_group %0;" :: "n"(N) : "memory");
}

// ---------------------------------------------------------------------------
// prep_kernel: fp32 -> fp16 conversion of x and W1 into global scratch.
// ---------------------------------------------------------------------------
__global__ __launch_bounds__(256) void prep_kernel(
    const float* __restrict__ x, const float* __restrict__ W1, int nx, int nw)
{
    int i = blockIdx.x * blockDim.x + threadIdx.x;
    int stride = gridDim.x * blockDim.x;
    __half2* xh2  = reinterpret_cast<__half2*>(g_xh);
    __half2* w1h2 = reinterpret_cast<__half2*>(g_w1h);
    const float4* x4 = (const float4*)x;
    const float4* w4 = (const float4*)W1;
    int nx4 = nx >> 2, nw4 = nw >> 2;
    for (int j = i; j < nx4; j += stride) {
        float4 v = x4[j];
        xh2[2*j]   = __floats2half2_rn(v.x, v.y);
        xh2[2*j+1] = __floats2half2_rn(v.z, v.w);
    }
    for (int j = i; j < nw4; j += stride) {
        float4 v = w4[j];
        w1h2[2*j]   = __floats2half2_rn(v.x, v.y);
        w1h2[2*j+1] = __floats2half2_rn(v.z, v.w);
    }
}

// ---------------------------------------------------------------------------
// main_kernel: Z = X @ W1^T (fp16 in, fp32 accum), y = x*softplus(Z+b1)*s.
// BM=BN=128, BK=32 halves. 128 threads = 4 warps (2x2), warp tile 64x64.
// Smem rows: 32 halves = 64B = 4x16B chunks; chunk swizzle p = c ^ ((r>>1)&3)
// -> conflict-free cp.async stores AND ldmatrix phases.
// 4-stage cp.async pipeline (16KB/stage), 2 CTAs/SM.
// ---------------------------------------------------------------------------
#define MS   4
#define MSTG 16384                 // bytes/stage: A 8KB + B 8KB

__global__ __launch_bounds__(128, 2) void main_kernel(
    const float* __restrict__ x, const float* __restrict__ b1,
    float* __restrict__ y, int T, int d)
{
    extern __shared__ char smem[];
    uint32_t sbase = (uint32_t)__cvta_generic_to_shared(smem);

    int tid  = threadIdx.x;
    int lane = tid & 31;
    int warp = tid >> 5;
    int wm   = warp >> 1;        // 0..1
    int wn   = warp & 1;         // 0..1
    int gid  = lane >> 2;        // 0..7
    int tig  = lane & 3;         // 0..3

    int bm = blockIdx.x * 128;
    int bn = blockIdx.y * 128;

    // ---- gmem->smem map: quad q = chunk, row = (tid>>2) + 32*j ----
    int q = tid & 3;
    int rowb = tid >> 2;           // 0..31
    uint32_t soff[4];
    #pragma unroll
    for (int j = 0; j < 4; j++) {
        int r = rowb + 32 * j;
        soff[j] = (uint32_t)(r * 64 + ((q ^ ((r >> 1) & 3)) << 4));
    }
    const __half* aptr = g_xh  + (size_t)(bm + rowb) * d + q * 8;
    const __half* bptr = g_w1h + (size_t)(bn + rowb) * d + q * 8;

    // ---- ldmatrix lane geometry ----
    int g = lane >> 3, lrow8 = lane & 7;
    uint32_t abase[4]; int axor[4];
    #pragma unroll
    for (int mi = 0; mi < 4; mi++) {
        int r = wm * 64 + mi * 16 + (g & 1) * 8 + lrow8;
        abase[mi] = (uint32_t)(r * 64);
        axor[mi]  = (r >> 1) & 3;
    }
    int acb = g >> 1;
    uint32_t bbase[4]; int bxor[4];
    #pragma unroll
    for (int nb = 0; nb < 4; nb++) {
        int r = wn * 64 + nb * 16 + (g >> 1) * 8 + lrow8;
        bbase[nb] = (uint32_t)(r * 64);
        bxor[nb]  = (r >> 1) & 3;
    }
    int bcb = g & 1;

    float acc[4][8][4];
    #pragma unroll
    for (int mi = 0; mi < 4; mi++)
        #pragma unroll
        for (int nj = 0; nj < 8; nj++)
            #pragma unroll
            for (int c = 0; c < 4; c++) acc[mi][nj][c] = 0.f;

    const int nslab = d / 32;      // 32

    // ---- prologue: stages 0..MS-2 ----
    #pragma unroll
    for (int j = 0; j < MS - 1; j++) {
        uint32_t sa = sbase + (uint32_t)(j * MSTG);
        uint32_t sb = sa + 8192u;
        int k0 = j * 32;
        #pragma unroll
        for (int jj = 0; jj < 4; jj++) {
            cp16(sa + soff[jj], aptr + (size_t)(32 * jj) * d + k0);
            cp16(sb + soff[jj], bptr + (size_t)(32 * jj) * d + k0);
        }
        cp_commit();
    }

    for (int i = 0; i < nslab; i++) {
        cp_wait<MS - 2>();
        __syncthreads();

        int jn = i + MS - 1;
        if (jn < nslab) {
            uint32_t sa = sbase + (uint32_t)((jn % MS) * MSTG);
            uint32_t sb = sa + 8192u;
            int k0 = jn * 32;
            #pragma unroll
            for (int jj = 0; jj < 4; jj++) {
                cp16(sa + soff[jj], aptr + (size_t)(32 * jj) * d + k0);
                cp16(sb + soff[jj], bptr + (size_t)(32 * jj) * d + k0);
            }
        }
        cp_commit();

        uint32_t sA = sbase + (uint32_t)((i % MS) * MSTG);
        uint32_t sB = sA + 8192u;

        #pragma unroll
        for (int h = 0; h < 2; h++) {
            int h2 = h * 2;
            uint32_t a[4][4], b[4][4];
            #pragma unroll
            for (int mi = 0; mi < 4; mi++)
                ldsm4(a[mi], sA + abase[mi] + (uint32_t)((((h2 + acb) ^ axor[mi])) << 4));
            #pragma unroll
            for (int nb = 0; nb < 4; nb++)
                ldsm4(b[nb], sB + bbase[nb] + (uint32_t)((((h2 + bcb) ^ bxor[nb])) << 4));
            #pragma unroll
            for (int mi = 0; mi < 4; mi++)
                #pragma unroll
                for (int nj = 0; nj < 8; nj++)
                    mma_f16(acc[mi][nj][0], acc[mi][nj][1],
                            acc[mi][nj][2], acc[mi][nj][3],
                            a[mi][0], a[mi][1], a[mi][2], a[mi][3],
                            b[nj >> 1][(nj & 1) * 2], b[nj >> 1][(nj & 1) * 2 + 1]);
        }
    }

    // ---- fused epilogue: y = x * softplus(z + b1) * s ----
    #pragma unroll
    for (int mi = 0; mi < 4; mi++) {
        int r0 = bm + wm * 64 + mi * 16 + gid;
        int r1 = r0 + 8;
        float sv0 = g_s[r0];
        float sv1 = g_s[r1];
        #pragma unroll
        for (int nj = 0; nj < 8; nj++) {
            int c0 = bn + wn * 64 + nj * 8 + tig * 2;
            float2 bias = *(const float2*)&b1[c0];
            float2 x0 = *(const float2*)&x[(size_t)r0 * d + c0];
            float2 x1 = *(const float2*)&x[(size_t)r1 * d + c0];
            float2 o0, o1;
            o0.x = x0.x * softplus_f(acc[mi][nj][0] + bias.x) * sv0;
            o0.y = x0.y * softplus_f(acc[mi][nj][1] + bias.y) * sv0;
            o1.x = x1.x * softplus_f(acc[mi][nj][2] + bias.x) * sv1;
            o1.y = x1.y * softplus_f(acc[mi][nj][3] + bias.y) * sv1;
            *(float2*)&y[(size_t)r0 * d + c0] = o0;
            *(float2*)&y[(size_t)r1 * d + c0] = o1;
        }
    }
}

// ---------------------------------------------------------------------------
// s_kernel: Z2 = X @ [W2;W3]^T (64 tokens/CTA, N=32, K=d), tf32 tensor cores,
// 4-stage cp.async pipeline; s from accumulator layout + shfl.  grid = T/64.
// (unchanged from R6 — known-good)
// ---------------------------------------------------------------------------
#define SS 4
#define SSTG 12288

__global__ __launch_bounds__(128, 2) void s_kernel(
    const float* __restrict__ x,
    const float* __restrict__ W2, const float* __restrict__ b2,
    const float* __restrict__ W3, const float* __restrict__ b3,
    int T, int d)
{
    extern __shared__ float smemf[];
    uint32_t sbase = (uint32_t)__cvta_generic_to_shared(smemf);

    int tid  = threadIdx.x;
    int lane = tid & 31;
    int w    = tid >> 5;
    int gid  = lane >> 2;
    int tig  = lane & 3;
    int t0   = blockIdx.x * 64;

    int lrow = tid >> 3;
    int lc4  = (tid & 7) * 4;
    uint32_t aoff[4], boff[2];
    #pragma unroll
    for (int j = 0; j < 4; j++) {
        int r = lrow + 16 * j;
        aoff[j] = (uint32_t)((r * 32 + (lc4 ^ ((r & 7) << 2))) * 4);
    }
    #pragma unroll
    for (int j = 0; j < 2; j++) {
        int r = lrow + 16 * j;
        boff[j] = (uint32_t)((r * 32 + (lc4 ^ ((r & 7) << 2))) * 4);
    }
    const float* xptr  = x  + (size_t)(t0 + lrow) * d + lc4;
    const float* wptr0 = W2 + (size_t)lrow * d + lc4;
    const float* wptr1 = W3 + (size_t)lrow * d + lc4;

    float acc[4][4];
    #pragma unroll
    for (int i = 0; i < 4; i++)
        #pragma unroll
        for (int c = 0; c < 4; c++) acc[i][c] = 0.f;

    const int nslab = d / 32;

    #pragma unroll
    for (int j = 0; j < SS - 1; j++) {
        uint32_t sa = sbase + (uint32_t)(j * SSTG);
        uint32_t sb = sa + 8192u;
        int k0 = j * 32;
        #pragma unroll
        for (int qq = 0; qq < 4; qq++)
            cp16(sa + aoff[qq], xptr + (size_t)(16 * qq) * d + k0);
        cp16(sb + boff[0], wptr0 + k0);
        cp16(sb + boff[1], wptr1 + k0);
        cp_commit();
    }

    int xr = gid << 2;

    for (int i = 0; i < nslab; i++) {
        cp_wait<SS - 2>();
        __syncthreads();

        int jn = i + SS - 1;
        if (jn < nslab) {
            uint32_t sa = sbase + (uint32_t)((jn % SS) * SSTG);
            uint32_t sb = sa + 8192u;
            int k0 = jn * 32;
            #pragma unroll
            for (int qq = 0; qq < 4; qq++)
                cp16(sa + aoff[qq], xptr + (size_t)(16 * qq) * d + k0);
            cp16(sb + boff[0], wptr0 + k0);
            cp16(sb + boff[1], wptr1 + k0);
        }
        cp_commit();

        const float* As = smemf + (size_t)(i % SS) * (SSTG / 4);
        const float* Bs = As + 2048;

        #pragma unroll
        for (int kk = 0; kk < 32; kk += 8) {
            int c1 = (kk + tig) ^ xr;
            int c2 = (kk + tig + 4) ^ xr;
            int r = w * 16 + gid;
            float a0 = tf32r(As[r * 32 + c1]);
            float a1 = tf32r(As[(r + 8) * 32 + c1]);
            float a2 = tf32r(As[r * 32 + c2]);
            float a3 = tf32r(As[(r + 8) * 32 + c2]);
            #pragma unroll
            for (int ni = 0; ni < 4; ni++) {
                int n = ni * 8 + gid;
                float b0 = tf32r(Bs[n * 32 + c1]);
                float b1v = tf32r(Bs[n * 32 + c2]);
                mma_tf32(acc[ni][0], acc[ni][1], acc[ni][2], acc[ni][3],
                         a0, a1, a2, a3, b0, b1v);
            }
        }
    }

    int nb0 = tig * 2, nb1 = nb0 + 1, nb2 = nb0 + 8, nb3 = nb0 + 9;
    float p2[4] = {b2[nb0], b2[nb1], b2[nb2], b2[nb3]};
    float p3[4] = {b3[nb0], b3[nb1], b3[nb2], b3[nb3]};

    #pragma unroll
    for (int h = 0; h < 2; h++) {
        float p =
            (acc[0][h*2+0] + p2[0]) * (acc[2][h*2+0] + p3[0]) +
            (acc[0][h*2+1] + p2[1]) * (acc[2][h*2+1] + p3[1]) +
            (acc[1][h*2+0] + p2[2]) * (acc[3][h*2+0] + p3[2]) +
            (acc[1][h*2+1] + p2[3]) * (acc[3][h*2+1] + p3[3]);
        p += __shfl_xor_sync(0xffffffffu, p, 1);
        p += __shfl_xor_sync(0xffffffffu, p, 2);
        if (tig == 0) {
            int t = t0 + w * 16 + gid + h * 8;
            if (t < T) g_s[t] = p;
        }
    }
}

// ---------------------------------------------------------------------------
// launch — inputs (metadata order): x, W1, b1, W2, b2, W3, b3, A
// ---------------------------------------------------------------------------
extern "C" void kernel_launch(void* const* d_in, const int* in_sizes, int n_in,
                              void* d_out, int out_size)
{
    const float* x  = (const float*)d_in[0];
    const float* W1 = (const float*)d_in[1];
    const float* b1 = (const float*)d_in[2];
    const float* W2 = (const float*)d_in[3];
    const float* b2 = (const float*)d_in[4];
    const float* W3 = (const float*)d_in[5];
    const float* b3 = (const float*)d_in[6];
    // d_in[7] = A: unused (h0 == 0 kills exp(dA)*h0 exactly)

    int d = in_sizes[2];          // d_model (1024)
    int T = in_sizes[0] / d;      // tokens (4096)
    float* y = (float*)d_out;

    const int SMEM_MAIN = MS * MSTG;   // 4 * 16KB = 64KB
    const int SMEM_S    = SS * SSTG;   // 4 * 12KB = 48KB

    cudaFuncSetAttribute(main_kernel, cudaFuncAttributeMaxDynamicSharedMemorySize, SMEM_MAIN);
    cudaFuncSetAttribute(s_kernel,    cudaFuncAttributeMaxDynamicSharedMemorySize, SMEM_S);

    prep_kernel<<<512, 256>>>(x, W1, T * d, d * d);
    s_kernel<<<T / 64, 128, SMEM_S>>>(x, W2, b2, W3, b3, T, d);
    dim3 grid(T / 128, d / 128);
    main_kernel<<<grid, 128, SMEM_MAIN>>>(x, b1, y, T, d);
}

// round 11
// speedup vs baseline: 3.2792x; 1.0406x over previous
#include <cuda_runtime.h>
#include <cuda_fp16.h>
#include <cstdint>
#include <cstddef>

// ============================================================================
// S6 reduced:  y[t,d] = x[t,d] * softplus((x@W1^T)[t,d] + b1[d]) * s[t]
//              s[t]   = sum_n (x@W2^T+b2)[t,n] * (x@W3^T+b3)[t,n]
// (h0 == 0 kills the exp(dA) term exactly; A unused.)
// T=4096, d=1024, n=16.
// Main GEMM: fp16 inputs (== tf32 precision) + fp32 accum, ldmatrix frags,
// 4-stage cp.async pipeline.  x->fp16 conversion fused into s_kernel (x tile
// is already staged in smem there); W1->fp16 in a tiny one-elem/thread prep.
// ============================================================================

#define MAX_T   4096
#define D_MODEL 1024

__device__ float g_s[MAX_T];
__device__ __align__(16) __half g_xh [MAX_T * D_MODEL];
__device__ __align__(16) __half g_w1h[D_MODEL * D_MODEL];

// ---------------------------------------------------------------------------
// helpers
// ---------------------------------------------------------------------------
__device__ __forceinline__ float tf32r(float f) {
    uint32_t r; asm("cvt.rna.tf32.f32 %0, %1;" : "=r"(r) : "f"(f));
    return __uint_as_float(r);
}
__device__ __forceinline__ float softplus_f(float z) {
    return fmaxf(z, 0.0f) + log1pf(expf(-fabsf(z)));
}
__device__ __forceinline__ void mma_tf32(float& c0, float& c1, float& c2, float& c3,
                                         float a0, float a1, float a2, float a3,
                                         float b0, float b1) {
    asm volatile(
        "mma.sync.aligned.m16n8k8.row.col.f32.tf32.tf32.f32 "
        "{%0,%1,%2,%3}, {%4,%5,%6,%7}, {%8,%9}, {%0,%1,%2,%3};\n"
        : "+f"(c0), "+f"(c1), "+f"(c2), "+f"(c3)
        : "r"(__float_as_uint(a0)), "r"(__float_as_uint(a1)),
          "r"(__float_as_uint(a2)), "r"(__float_as_uint(a3)),
          "r"(__float_as_uint(b0)), "r"(__float_as_uint(b1)));
}
__device__ __forceinline__ void mma_f16(float& c0, float& c1, float& c2, float& c3,
                                        uint32_t a0, uint32_t a1, uint32_t a2, uint32_t a3,
                                        uint32_t b0, uint32_t b1) {
    asm volatile(
        "mma.sync.aligned.m16n8k16.row.col.f32.f16.f16.f32 "
        "{%0,%1,%2,%3}, {%4,%5,%6,%7}, {%8,%9}, {%0,%1,%2,%3};\n"
        : "+f"(c0), "+f"(c1), "+f"(c2), "+f"(c3)
        : "r"(a0), "r"(a1), "r"(a2), "r"(a3), "r"(b0), "r"(b1));
}
__device__ __forceinline__ void ldsm4(uint32_t* r, uint32_t addr) {
    asm volatile("ldmatrix.sync.aligned.m8n8.x4.shared.b16 {%0,%1,%2,%3}, [%4];"
                 : "=r"(r[0]), "=r"(r[1]), "=r"(r[2]), "=r"(r[3]) : "r"(addr));
}
__device__ __forceinline__ void cp16(uint32_t dst_smem, const void* src) {
    asm volatile("cp.async.cg.shared.global [%0], [%1], 16;"
                 :: "r"(dst_smem), "l"(src));
}
__device__ __forceinline__ void cp_commit() {
    asm volatile("cp.async.commit_group;");
}
template <int N>
__device__ __forceinline__ void cp_wait() {
    asm volatile("cp.async.wait_group %0;" :: "n"(N) : "memory");
}

// ---------------------------------------------------------------------------
// prep_w1: fp32 -> fp16 for W1 only; exactly one float4 per thread (max MLP).
// ---------------------------------------------------------------------------
__global__ __launch_bounds__(256) void prep_w1(const float* __restrict__ W1)
{
    int j = blockIdx.x * blockDim.x + threadIdx.x;   // float4 index
    float4 v = ((const float4*)W1)[j];
    __half2 h0 = __floats2half2_rn(v.x, v.y);
    __half2 h1 = __floats2half2_rn(v.z, v.w);
    uint2 pk;
    pk.x = *(uint32_t*)&h0;
    pk.y = *(uint32_t*)&h1;
    ((uint2*)g_w1h)[j] = pk;
}

// ---------------------------------------------------------------------------
// s_kernel: Z2 = X @ [W2;W3]^T (64 tokens/CTA, N=32, K=d), tf32 tensor cores,
// 4-stage cp.async pipeline; s from accumulator layout + shfl.  grid = T/64.
// FUSED: converts each staged x tile to fp16 -> g_xh (x read shared).
// ---------------------------------------------------------------------------
#define SS 4
#define SSTG 12288

__global__ __launch_bounds__(128, 2) void s_kernel(
    const float* __restrict__ x,
    const float* __restrict__ W2, const float* __restrict__ b2,
    const float* __restrict__ W3, const float* __restrict__ b3,
    int T, int d)
{
    extern __shared__ float smemf[];
    uint32_t sbase = (uint32_t)__cvta_generic_to_shared(smemf);

    int tid  = threadIdx.x;
    int lane = tid & 31;
    int w    = tid >> 5;
    int gid  = lane >> 2;
    int tig  = lane & 3;
    int t0   = blockIdx.x * 64;

    int lrow = tid >> 3;
    int lc4  = (tid & 7) * 4;
    uint32_t aoff[4], boff[2];
    int aswz[4];
    #pragma unroll
    for (int j = 0; j < 4; j++) {
        int r = lrow + 16 * j;
        aswz[j] = lc4 ^ ((r & 7) << 2);
        aoff[j] = (uint32_t)((r * 32 + aswz[j]) * 4);
    }
    #pragma unroll
    for (int j = 0; j < 2; j++) {
        int r = lrow + 16 * j;
        boff[j] = (uint32_t)((r * 32 + (lc4 ^ ((r & 7) << 2))) * 4);
    }
    const float* xptr  = x  + (size_t)(t0 + lrow) * d + lc4;
    const float* wptr0 = W2 + (size_t)lrow * d + lc4;
    const float* wptr1 = W3 + (size_t)lrow * d + lc4;

    float acc[4][4];
    #pragma unroll
    for (int i = 0; i < 4; i++)
        #pragma unroll
        for (int c = 0; c < 4; c++) acc[i][c] = 0.f;

    const int nslab = d / 32;

    #pragma unroll
    for (int j = 0; j < SS - 1; j++) {
        uint32_t sa = sbase + (uint32_t)(j * SSTG);
        uint32_t sb = sa + 8192u;
        int k0 = j * 32;
        #pragma unroll
        for (int qq = 0; qq < 4; qq++)
            cp16(sa + aoff[qq], xptr + (size_t)(16 * qq) * d + k0);
        cp16(sb + boff[0], wptr0 + k0);
        cp16(sb + boff[1], wptr1 + k0);
        cp_commit();
    }

    int xr = gid << 2;

    for (int i = 0; i < nslab; i++) {
        cp_wait<SS - 2>();
        __syncthreads();

        int jn = i + SS - 1;
        if (jn < nslab) {
            uint32_t sa = sbase + (uint32_t)((jn % SS) * SSTG);
            uint32_t sb = sa + 8192u;
            int k0 = jn * 32;
            #pragma unroll
            for (int qq = 0; qq < 4; qq++)
                cp16(sa + aoff[qq], xptr + (size_t)(16 * qq) * d + k0);
            cp16(sb + boff[0], wptr0 + k0);
            cp16(sb + boff[1], wptr1 + k0);
        }
        cp_commit();

        const float* As = smemf + (size_t)(i % SS) * (SSTG / 4);
        const float* Bs = As + 2048;

        // ---- fused x -> fp16 conversion of this slab (x already in smem) ----
        {
            int k0 = i * 32;
            #pragma unroll
            for (int j = 0; j < 4; j++) {
                int r = lrow + 16 * j;
                float4 v = *(const float4*)(As + r * 32 + aswz[j]);
                __half2 h0 = __floats2half2_rn(v.x, v.y);
                __half2 h1 = __floats2half2_rn(v.z, v.w);
                uint2 pk;
                pk.x = *(uint32_t*)&h0;
                pk.y = *(uint32_t*)&h1;
                *(uint2*)(g_xh + (size_t)(t0 + r) * d + k0 + lc4) = pk;
            }
        }

        #pragma unroll
        for (int kk = 0; kk < 32; kk += 8) {
            int c1 = (kk + tig) ^ xr;
            int c2 = (kk + tig + 4) ^ xr;
            int r = w * 16 + gid;
            float a0 = tf32r(As[r * 32 + c1]);
            float a1 = tf32r(As[(r + 8) * 32 + c1]);
            float a2 = tf32r(As[r * 32 + c2]);
            float a3 = tf32r(As[(r + 8) * 32 + c2]);
            #pragma unroll
            for (int ni = 0; ni < 4; ni++) {
                int n = ni * 8 + gid;
                float b0 = tf32r(Bs[n * 32 + c1]);
                float b1v = tf32r(Bs[n * 32 + c2]);
                mma_tf32(acc[ni][0], acc[ni][1], acc[ni][2], acc[ni][3],
                         a0, a1, a2, a3, b0, b1v);
            }
        }
    }

    int nb0 = tig * 2, nb1 = nb0 + 1, nb2 = nb0 + 8, nb3 = nb0 + 9;
    float p2[4] = {b2[nb0], b2[nb1], b2[nb2], b2[nb3]};
    float p3[4] = {b3[nb0], b3[nb1], b3[nb2], b3[nb3]};

    #pragma unroll
    for (int h = 0; h < 2; h++) {
        float p =
            (acc[0][h*2+0] + p2[0]) * (acc[2][h*2+0] + p3[0]) +
            (acc[0][h*2+1] + p2[1]) * (acc[2][h*2+1] + p3[1]) +
            (acc[1][h*2+0] + p2[2]) * (acc[3][h*2+0] + p3[2]) +
            (acc[1][h*2+1] + p2[3]) * (acc[3][h*2+1] + p3[3]);
        p += __shfl_xor_sync(0xffffffffu, p, 1);
        p += __shfl_xor_sync(0xffffffffu, p, 2);
        if (tig == 0) {
            int t = t0 + w * 16 + gid + h * 8;
            if (t < T) g_s[t] = p;
        }
    }
}

// ---------------------------------------------------------------------------
// main_kernel: Z = X @ W1^T (fp16 in, fp32 accum), y = x*softplus(Z+b1)*s.
// BM=BN=128, BK=32 halves. 128 threads = 4 warps (2x2), warp tile 64x64.
// Chunk swizzle p = c ^ ((r>>1)&3): conflict-free cp.async + ldmatrix.
// 4-stage cp.async pipeline (16KB/stage), 2 CTAs/SM.
// ---------------------------------------------------------------------------
#define MS   4
#define MSTG 16384                 // bytes/stage: A 8KB + B 8KB

__global__ __launch_bounds__(128, 2) void main_kernel(
    const float* __restrict__ x, const float* __restrict__ b1,
    float* __restrict__ y, int T, int d)
{
    extern __shared__ char smem[];
    uint32_t sbase = (uint32_t)__cvta_generic_to_shared(smem);

    int tid  = threadIdx.x;
    int lane = tid & 31;
    int warp = tid >> 5;
    int wm   = warp >> 1;        // 0..1
    int wn   = warp & 1;         // 0..1
    int gid  = lane >> 2;        // 0..7
    int tig  = lane & 3;         // 0..3

    int bm = blockIdx.x * 128;
    int bn = blockIdx.y * 128;

    // ---- gmem->smem map: quad q = chunk, row = (tid>>2) + 32*j ----
    int q = tid & 3;
    int rowb = tid >> 2;           // 0..31
    uint32_t soff[4];
    #pragma unroll
    for (int j = 0; j < 4; j++) {
        int r = rowb + 32 * j;
        soff[j] = (uint32_t)(r * 64 + ((q ^ ((r >> 1) & 3)) << 4));
    }
    const __half* aptr = g_xh  + (size_t)(bm + rowb) * d + q * 8;
    const __half* bptr = g_w1h + (size_t)(bn + rowb) * d + q * 8;

    // ---- ldmatrix lane geometry ----
    int g = lane >> 3, lrow8 = lane & 7;
    uint32_t abase[4]; int axor[4];
    #pragma unroll
    for (int mi = 0; mi < 4; mi++) {
        int r = wm * 64 + mi * 16 + (g & 1) * 8 + lrow8;
        abase[mi] = (uint32_t)(r * 64);
        axor[mi]  = (r >> 1) & 3;
    }
    int acb = g >> 1;
    uint32_t bbase[4]; int bxor[4];
    #pragma unroll
    for (int nb = 0; nb < 4; nb++) {
        int r = wn * 64 + nb * 16 + (g >> 1) * 8 + lrow8;
        bbase[nb] = (uint32_t)(r * 64);
        bxor[nb]  = (r >> 1) & 3;
    }
    int bcb = g & 1;

    float acc[4][8][4];
    #pragma unroll
    for (int mi = 0; mi < 4; mi++)
        #pragma unroll
        for (int nj = 0; nj < 8; nj++)
            #pragma unroll
            for (int c = 0; c < 4; c++) acc[mi][nj][c] = 0.f;

    const int nslab = d / 32;      // 32

    // ---- prologue: stages 0..MS-2 ----
    #pragma unroll
    for (int j = 0; j < MS - 1; j++) {
        uint32_t sa = sbase + (uint32_t)(j * MSTG);
        uint32_t sb = sa + 8192u;
        int k0 = j * 32;
        #pragma unroll
        for (int jj = 0; jj < 4; jj++) {
            cp16(sa + soff[jj], aptr + (size_t)(32 * jj) * d + k0);
            cp16(sb + soff[jj], bptr + (size_t)(32 * jj) * d + k0);
        }
        cp_commit();
    }

    for (int i = 0; i < nslab; i++) {
        cp_wait<MS - 2>();
        __syncthreads();

        int jn = i + MS - 1;
        if (jn < nslab) {
            uint32_t sa = sbase + (uint32_t)((jn % MS) * MSTG);
            uint32_t sb = sa + 8192u;
            int k0 = jn * 32;
            #pragma unroll
            for (int jj = 0; jj < 4; jj++) {
                cp16(sa + soff[jj], aptr + (size_t)(32 * jj) * d + k0);
                cp16(sb + soff[jj], bptr + (size_t)(32 * jj) * d + k0);
            }
        }
        cp_commit();

        uint32_t sA = sbase + (uint32_t)((i % MS) * MSTG);
        uint32_t sB = sA + 8192u;

        #pragma unroll
        for (int h = 0; h < 2; h++) {
            int h2 = h * 2;
            uint32_t a[4][4], b[4][4];
            #pragma unroll
            for (int mi = 0; mi < 4; mi++)
                ldsm4(a[mi], sA + abase[mi] + (uint32_t)((((h2 + acb) ^ axor[mi])) << 4));
            #pragma unroll
            for (int nb = 0; nb < 4; nb++)
                ldsm4(b[nb], sB + bbase[nb] + (uint32_t)((((h2 + bcb) ^ bxor[nb])) << 4));
            #pragma unroll
            for (int mi = 0; mi < 4; mi++)
                #pragma unroll
                for (int nj = 0; nj < 8; nj++)
                    mma_f16(acc[mi][nj][0], acc[mi][nj][1],
                            acc[mi][nj][2], acc[mi][nj][3],
                            a[mi][0], a[mi][1], a[mi][2], a[mi][3],
                            b[nj >> 1][(nj & 1) * 2], b[nj >> 1][(nj & 1) * 2 + 1]);
        }
    }

    // ---- fused epilogue: y = x * softplus(z + b1) * s ----
    #pragma unroll
    for (int mi = 0; mi < 4; mi++) {
        int r0 = bm + wm * 64 + mi * 16 + gid;
        int r1 = r0 + 8;
        float sv0 = g_s[r0];
        float sv1 = g_s[r1];
        #pragma unroll
        for (int nj = 0; nj < 8; nj++) {
            int c0 = bn + wn * 64 + nj * 8 + tig * 2;
            float2 bias = *(const float2*)&b1[c0];
            float2 x0 = *(const float2*)&x[(size_t)r0 * d + c0];
            float2 x1 = *(const float2*)&x[(size_t)r1 * d + c0];
            float2 o0, o1;
            o0.x = x0.x * softplus_f(acc[mi][nj][0] + bias.x) * sv0;
            o0.y = x0.y * softplus_f(acc[mi][nj][1] + bias.y) * sv0;
            o1.x = x1.x * softplus_f(acc[mi][nj][2] + bias.x) * sv1;
            o1.y = x1.y * softplus_f(acc[mi][nj][3] + bias.y) * sv1;
            *(float2*)&y[(size_t)r0 * d + c0] = o0;
            *(float2*)&y[(size_t)r1 * d + c0] = o1;
        }
    }
}

// ---------------------------------------------------------------------------
// launch — inputs (metadata order): x, W1, b1, W2, b2, W3, b3, A
// ---------------------------------------------------------------------------
extern "C" void kernel_launch(void* const* d_in, const int* in_sizes, int n_in,
                              void* d_out, int out_size)
{
    const float* x  = (const float*)d_in[0];
    const float* W1 = (const float*)d_in[1];
    const float* b1 = (const float*)d_in[2];
    const float* W2 = (const float*)d_in[3];
    const float* b2 = (const float*)d_in[4];
    const float* W3 = (const float*)d_in[5];
    const float* b3 = (const float*)d_in[6];
    // d_in[7] = A: unused (h0 == 0 kills exp(dA)*h0 exactly)

    int d = in_sizes[2];          // d_model (1024)
    int T = in_sizes[0] / d;      // tokens (4096)
    float* y = (float*)d_out;

    const int SMEM_MAIN = MS * MSTG;   // 4 * 16KB = 64KB
    const int SMEM_S    = SS * SSTG;   // 4 * 12KB = 48KB

    cudaFuncSetAttribute(main_kernel, cudaFuncAttributeMaxDynamicSharedMemorySize, SMEM_MAIN);
    cudaFuncSetAttribute(s_kernel,    cudaFuncAttributeMaxDynamicSharedMemorySize, SMEM_S);

    prep_w1<<<(d * d / 4) / 256, 256>>>(W1);
    s_kernel<<<T / 64, 128, SMEM_S>>>(x, W2, b2, W3, b3, T, d);
    dim3 grid(T / 128, d / 128);
    main_kernel<<<grid, 128, SMEM_MAIN>>>(x, b1, y, T, d);
}

// round 12
// speedup vs baseline: 3.3849x; 1.0322x over previous
#include <cuda_runtime.h>
#include <cuda_fp16.h>
#include <cstdint>
#include <cstddef>

// ============================================================================
// S6 reduced:  y[t,d] = x[t,d] * softplus((x@W1^T)[t,d] + b1[d]) * s[t]
//              s[t]   = sum_n (x@W2^T+b2)[t,n] * (x@W3^T+b3)[t,n]
// (h0 == 0 kills the exp(dA) term exactly; A unused.)
// T=4096, d=1024, n=16.
// Main GEMM: fp16 inputs (== tf32 precision) + fp32 accum, ldmatrix frags,
// BK=64 slabs, 3-stage cp.async pipeline.  x->fp16 AND W1->fp16 conversions
// both fused into s_kernel (no separate prep launch).
// ============================================================================

#define MAX_T   4096
#define D_MODEL 1024

__device__ float g_s[MAX_T];
__device__ __align__(16) __half g_xh [MAX_T * D_MODEL];
__device__ __align__(16) __half g_w1h[D_MODEL * D_MODEL];

// ---------------------------------------------------------------------------
// helpers
// ---------------------------------------------------------------------------
__device__ __forceinline__ float tf32r(float f) {
    uint32_t r; asm("cvt.rna.tf32.f32 %0, %1;" : "=r"(r) : "f"(f));
    return __uint_as_float(r);
}
__device__ __forceinline__ float softplus_f(float z) {
    return fmaxf(z, 0.0f) + log1pf(expf(-fabsf(z)));
}
__device__ __forceinline__ void mma_tf32(float& c0, float& c1, float& c2, float& c3,
                                         float a0, float a1, float a2, float a3,
                                         float b0, float b1) {
    asm volatile(
        "mma.sync.aligned.m16n8k8.row.col.f32.tf32.tf32.f32 "
        "{%0,%1,%2,%3}, {%4,%5,%6,%7}, {%8,%9}, {%0,%1,%2,%3};\n"
        : "+f"(c0), "+f"(c1), "+f"(c2), "+f"(c3)
        : "r"(__float_as_uint(a0)), "r"(__float_as_uint(a1)),
          "r"(__float_as_uint(a2)), "r"(__float_as_uint(a3)),
          "r"(__float_as_uint(b0)), "r"(__float_as_uint(b1)));
}
__device__ __forceinline__ void mma_f16(float& c0, float& c1, float& c2, float& c3,
                                        uint32_t a0, uint32_t a1, uint32_t a2, uint32_t a3,
                                        uint32_t b0, uint32_t b1) {
    asm volatile(
        "mma.sync.aligned.m16n8k16.row.col.f32.f16.f16.f32 "
        "{%0,%1,%2,%3}, {%4,%5,%6,%7}, {%8,%9}, {%0,%1,%2,%3};\n"
        : "+f"(c0), "+f"(c1), "+f"(c2), "+f"(c3)
        : "r"(a0), "r"(a1), "r"(a2), "r"(a3), "r"(b0), "r"(b1));
}
__device__ __forceinline__ void ldsm4(uint32_t* r, uint32_t addr) {
    asm volatile("ldmatrix.sync.aligned.m8n8.x4.shared.b16 {%0,%1,%2,%3}, [%4];"
                 : "=r"(r[0]), "=r"(r[1]), "=r"(r[2]), "=r"(r[3]) : "r"(addr));
}
__device__ __forceinline__ void cp16(uint32_t dst_smem, const void* src) {
    asm volatile("cp.async.cg.shared.global [%0], [%1], 16;"
                 :: "r"(dst_smem), "l"(src));
}
__device__ __forceinline__ void cp_commit() {
    asm volatile("cp.async.commit_group;");
}
template <int N>
__device__ __forceinline__ void cp_wait() {
    asm volatile("cp.async.wait_group %0;" :: "n"(N) : "memory");
}

// ---------------------------------------------------------------------------
// s_kernel: Z2 = X @ [W2;W3]^T (64 tokens/CTA, N=32, K=d), tf32 tensor cores,
// 4-stage cp.async pipeline; s from accumulator layout + shfl.  grid = T/64.
// FUSED: per-slab x tile -> fp16 (x already staged in smem) and a strided
// 1-float4/thread W1 -> fp16 conversion (replaces the prep kernel).
// ---------------------------------------------------------------------------
#define SS 4
#define SSTG 12288

__global__ __launch_bounds__(128, 2) void s_kernel(
    const float* __restrict__ x,
    const float* __restrict__ W2, const float* __restrict__ b2,
    const float* __restrict__ W3, const float* __restrict__ b3,
    const float* __restrict__ W1,
    int T, int d)
{
    extern __shared__ float smemf[];
    uint32_t sbase = (uint32_t)__cvta_generic_to_shared(smemf);

    int tid  = threadIdx.x;
    int lane = tid & 31;
    int w    = tid >> 5;
    int gid  = lane >> 2;
    int tig  = lane & 3;
    int t0   = blockIdx.x * 64;

    int lrow = tid >> 3;
    int lc4  = (tid & 7) * 4;
    uint32_t aoff[4], boff[2];
    int aswz[4];
    #pragma unroll
    for (int j = 0; j < 4; j++) {
        int r = lrow + 16 * j;
        aswz[j] = lc4 ^ ((r & 7) << 2);
        aoff[j] = (uint32_t)((r * 32 + aswz[j]) * 4);
    }
    #pragma unroll
    for (int j = 0; j < 2; j++) {
        int r = lrow + 16 * j;
        boff[j] = (uint32_t)((r * 32 + (lc4 ^ ((r & 7) << 2))) * 4);
    }
    const float* xptr  = x  + (size_t)(t0 + lrow) * d + lc4;
    const float* wptr0 = W2 + (size_t)lrow * d + lc4;
    const float* wptr1 = W3 + (size_t)lrow * d + lc4;

    float acc[4][4];
    #pragma unroll
    for (int i = 0; i < 4; i++)
        #pragma unroll
        for (int c = 0; c < 4; c++) acc[i][c] = 0.f;

    const int nslab = d / 32;                       // 32
    const int nthreads_total = (T / 64) * 128;      // grid threads (8192)
    int gtid = blockIdx.x * 128 + tid;

    #pragma unroll
    for (int j = 0; j < SS - 1; j++) {
        uint32_t sa = sbase + (uint32_t)(j * SSTG);
        uint32_t sb = sa + 8192u;
        int k0 = j * 32;
        #pragma unroll
        for (int qq = 0; qq < 4; qq++)
            cp16(sa + aoff[qq], xptr + (size_t)(16 * qq) * d + k0);
        cp16(sb + boff[0], wptr0 + k0);
        cp16(sb + boff[1], wptr1 + k0);
        cp_commit();
    }

    int xr = gid << 2;

    for (int i = 0; i < nslab; i++) {
        cp_wait<SS - 2>();
        __syncthreads();

        int jn = i + SS - 1;
        if (jn < nslab) {
            uint32_t sa = sbase + (uint32_t)((jn % SS) * SSTG);
            uint32_t sb = sa + 8192u;
            int k0 = jn * 32;
            #pragma unroll
            for (int qq = 0; qq < 4; qq++)
                cp16(sa + aoff[qq], xptr + (size_t)(16 * qq) * d + k0);
            cp16(sb + boff[0], wptr0 + k0);
            cp16(sb + boff[1], wptr1 + k0);
        }
        cp_commit();

        // ---- fused W1 -> fp16: one float4 per thread per slab ----
        {
            int idx = i * nthreads_total + gtid;    // covers d*d/4 float4s
            float4 v = ((const float4*)W1)[idx];
            __half2 h0 = __floats2half2_rn(v.x, v.y);
            __half2 h1 = __floats2half2_rn(v.z, v.w);
            uint2 pk;
            pk.x = *(uint32_t*)&h0;
            pk.y = *(uint32_t*)&h1;
            ((uint2*)g_w1h)[idx] = pk;
        }

        const float* As = smemf + (size_t)(i % SS) * (SSTG / 4);
        const float* Bs = As + 2048;

        // ---- fused x -> fp16 conversion of this slab (x already in smem) ----
        {
            int k0 = i * 32;
            #pragma unroll
            for (int j = 0; j < 4; j++) {
                int r = lrow + 16 * j;
                float4 v = *(const float4*)(As + r * 32 + aswz[j]);
                __half2 h0 = __floats2half2_rn(v.x, v.y);
                __half2 h1 = __floats2half2_rn(v.z, v.w);
                uint2 pk;
                pk.x = *(uint32_t*)&h0;
                pk.y = *(uint32_t*)&h1;
                *(uint2*)(g_xh + (size_t)(t0 + r) * d + k0 + lc4) = pk;
            }
        }

        #pragma unroll
        for (int kk = 0; kk < 32; kk += 8) {
            int c1 = (kk + tig) ^ xr;
            int c2 = (kk + tig + 4) ^ xr;
            int r = w * 16 + gid;
            float a0 = tf32r(As[r * 32 + c1]);
            float a1 = tf32r(As[(r + 8) * 32 + c1]);
            float a2 = tf32r(As[r * 32 + c2]);
            float a3 = tf32r(As[(r + 8) * 32 + c2]);
            #pragma unroll
            for (int ni = 0; ni < 4; ni++) {
                int n = ni * 8 + gid;
                float b0 = tf32r(Bs[n * 32 + c1]);
                float b1v = tf32r(Bs[n * 32 + c2]);
                mma_tf32(acc[ni][0], acc[ni][1], acc[ni][2], acc[ni][3],
                         a0, a1, a2, a3, b0, b1v);
            }
        }
    }

    int nb0 = tig * 2, nb1 = nb0 + 1, nb2 = nb0 + 8, nb3 = nb0 + 9;
    float p2[4] = {b2[nb0], b2[nb1], b2[nb2], b2[nb3]};
    float p3[4] = {b3[nb0], b3[nb1], b3[nb2], b3[nb3]};

    #pragma unroll
    for (int h = 0; h < 2; h++) {
        float p =
            (acc[0][h*2+0] + p2[0]) * (acc[2][h*2+0] + p3[0]) +
            (acc[0][h*2+1] + p2[1]) * (acc[2][h*2+1] + p3[1]) +
            (acc[1][h*2+0] + p2[2]) * (acc[3][h*2+0] + p3[2]) +
            (acc[1][h*2+1] + p2[3]) * (acc[3][h*2+1] + p3[3]);
        p += __shfl_xor_sync(0xffffffffu, p, 1);
        p += __shfl_xor_sync(0xffffffffu, p, 2);
        if (tig == 0) {
            int t = t0 + w * 16 + gid + h * 8;
            if (t < T) g_s[t] = p;
        }
    }
}

// ---------------------------------------------------------------------------
// main_kernel: Z = X @ W1^T (fp16 in, fp32 accum), y = x*softplus(Z+b1)*s.
// BM=BN=128, BK=64 halves (128B rows, 8 chunks). 128 threads = 4 warps (2x2),
// warp tile 64x64.  Chunk swizzle p = c ^ (r&7): conflict-free cp.async
// stores AND ldmatrix phases.  3-stage pipeline (32KB/stage), 2 CTAs/SM.
// 16 slabs -> half the barriers of BK=32.
// ---------------------------------------------------------------------------
#define MS   3
#define MSTG 32768                 // bytes/stage: A 16KB + B 16KB

__global__ __launch_bounds__(128, 2) void main_kernel(
    const float* __restrict__ x, const float* __restrict__ b1,
    float* __restrict__ y, int T, int d)
{
    extern __shared__ char smem[];
    uint32_t sbase = (uint32_t)__cvta_generic_to_shared(smem);

    int tid  = threadIdx.x;
    int lane = tid & 31;
    int warp = tid >> 5;
    int wm   = warp >> 1;        // 0..1
    int wn   = warp & 1;         // 0..1
    int gid  = lane >> 2;        // 0..7
    int tig  = lane & 3;         // 0..3

    int bm = blockIdx.x * 128;
    int bn = blockIdx.y * 128;

    // ---- gmem->smem map: chunk q = tid&7, row = (tid>>3) + 16*j, j=0..7 ----
    int q    = tid & 7;
    int rowb = tid >> 3;           // 0..15
    uint32_t soff[8];
    #pragma unroll
    for (int j = 0; j < 8; j++) {
        int r = rowb + 16 * j;
        soff[j] = (uint32_t)(r * 128 + ((q ^ (r & 7)) << 4));
    }
    const __half* aptr = g_xh  + (size_t)(bm + rowb) * d + q * 8;
    const __half* bptr = g_w1h + (size_t)(bn + rowb) * d + q * 8;

    // ---- ldmatrix lane geometry ----
    int g = lane >> 3, lrow8 = lane & 7;
    uint32_t abase[4]; int axor[4];
    #pragma unroll
    for (int mi = 0; mi < 4; mi++) {
        int r = wm * 64 + mi * 16 + (g & 1) * 8 + lrow8;
        abase[mi] = (uint32_t)(r * 128);
        axor[mi]  = r & 7;
    }
    int acb = g >> 1;
    uint32_t bbase[4]; int bxor[4];
    #pragma unroll
    for (int nb = 0; nb < 4; nb++) {
        int r = wn * 64 + nb * 16 + (g >> 1) * 8 + lrow8;
        bbase[nb] = (uint32_t)(r * 128);
        bxor[nb]  = r & 7;
    }
    int bcb = g & 1;

    float acc[4][8][4];
    #pragma unroll
    for (int mi = 0; mi < 4; mi++)
        #pragma unroll
        for (int nj = 0; nj < 8; nj++)
            #pragma unroll
            for (int c = 0; c < 4; c++) acc[mi][nj][c] = 0.f;

    const int nslab = d / 64;      // 16

    // ---- prologue: stages 0..MS-2 ----
    #pragma unroll
    for (int j = 0; j < MS - 1; j++) {
        uint32_t sa = sbase + (uint32_t)(j * MSTG);
        uint32_t sb = sa + 16384u;
        int k0 = j * 64;
        #pragma unroll
        for (int jj = 0; jj < 8; jj++) {
            cp16(sa + soff[jj], aptr + (size_t)(16 * jj) * d + k0);
            cp16(sb + soff[jj], bptr + (size_t)(16 * jj) * d + k0);
        }
        cp_commit();
    }

    for (int i = 0; i < nslab; i++) {
        cp_wait<MS - 2>();
        __syncthreads();

        int jn = i + MS - 1;
        if (jn < nslab) {
            uint32_t sa = sbase + (uint32_t)((jn % MS) * MSTG);
            uint32_t sb = sa + 16384u;
            int k0 = jn * 64;
            #pragma unroll
            for (int jj = 0; jj < 8; jj++) {
                cp16(sa + soff[jj], aptr + (size_t)(16 * jj) * d + k0);
                cp16(sb + soff[jj], bptr + (size_t)(16 * jj) * d + k0);
            }
        }
        cp_commit();

        uint32_t sA = sbase + (uint32_t)((i % MS) * MSTG);
        uint32_t sB = sA + 16384u;

        #pragma unroll
        for (int kk = 0; kk < 4; kk++) {
            int c2 = kk * 2;
            uint32_t a[4][4], b[4][4];
            #pragma unroll
            for (int mi = 0; mi < 4; mi++)
                ldsm4(a[mi], sA + abase[mi] + (uint32_t)((((c2 + acb) ^ axor[mi])) << 4));
            #pragma unroll
            for (int nb = 0; nb < 4; nb++)
                ldsm4(b[nb], sB + bbase[nb] + (uint32_t)((((c2 + bcb) ^ bxor[nb])) << 4));
            #pragma unroll
            for (int mi = 0; mi < 4; mi++)
                #pragma unroll
                for (int nj = 0; nj < 8; nj++)
                    mma_f16(acc[mi][nj][0], acc[mi][nj][1],
                            acc[mi][nj][2], acc[mi][nj][3],
                            a[mi][0], a[mi][1], a[mi][2], a[mi][3],
                            b[nj >> 1][(nj & 1) * 2], b[nj >> 1][(nj & 1) * 2 + 1]);
        }
    }

    // ---- fused epilogue: y = x * softplus(z + b1) * s ----
    #pragma unroll
    for (int mi = 0; mi < 4; mi++) {
        int r0 = bm + wm * 64 + mi * 16 + gid;
        int r1 = r0 + 8;
        float sv0 = g_s[r0];
        float sv1 = g_s[r1];
        #pragma unroll
        for (int nj = 0; nj < 8; nj++) {
            int c0 = bn + wn * 64 + nj * 8 + tig * 2;
            float2 bias = *(const float2*)&b1[c0];
            float2 x0 = *(const float2*)&x[(size_t)r0 * d + c0];
            float2 x1 = *(const float2*)&x[(size_t)r1 * d + c0];
            float2 o0, o1;
            o0.x = x0.x * softplus_f(acc[mi][nj][0] + bias.x) * sv0;
            o0.y = x0.y * softplus_f(acc[mi][nj][1] + bias.y) * sv0;
            o1.x = x1.x * softplus_f(acc[mi][nj][2] + bias.x) * sv1;
            o1.y = x1.y * softplus_f(acc[mi][nj][3] + bias.y) * sv1;
            *(float2*)&y[(size_t)r0 * d + c0] = o0;
            *(float2*)&y[(size_t)r1 * d + c0] = o1;
        }
    }
}

// ---------------------------------------------------------------------------
// launch — inputs (metadata order): x, W1, b1, W2, b2, W3, b3, A
// ---------------------------------------------------------------------------
extern "C" void kernel_launch(void* const* d_in, const int* in_sizes, int n_in,
                              void* d_out, int out_size)
{
    const float* x  = (const float*)d_in[0];
    const float* W1 = (const float*)d_in[1];
    const float* b1 = (const float*)d_in[2];
    const float* W2 = (const float*)d_in[3];
    const float* b2 = (const float*)d_in[4];
    const float* W3 = (const float*)d_in[5];
    const float* b3 = (const float*)d_in[6];
    // d_in[7] = A: unused (h0 == 0 kills exp(dA)*h0 exactly)

    int d = in_sizes[2];          // d_model (1024)
    int T = in_sizes[0] / d;      // tokens (4096)
    float* y = (float*)d_out;

    const int SMEM_MAIN = MS * MSTG;   // 3 * 32KB = 96KB
    const int SMEM_S    = SS * SSTG;   // 4 * 12KB = 48KB

    cudaFuncSetAttribute(main_kernel, cudaFuncAttributeMaxDynamicSharedMemorySize, SMEM_MAIN);
    cudaFuncSetAttribute(s_kernel,    cudaFuncAttributeMaxDynamicSharedMemorySize, SMEM_S);

    s_kernel<<<T / 64, 128, SMEM_S>>>(x, W2, b2, W3, b3, W1, T, d);
    dim3 grid(T / 128, d / 128);
    main_kernel<<<grid, 128, SMEM_MAIN>>>(x, b1, y, T, d);
}

// round 13
// speedup vs baseline: 3.8603x; 1.1404x over previous
#include <cuda_runtime.h>
#include <cuda_fp16.h>
#include <cstdint>
#include <cstddef>

// ============================================================================
// S6 reduced:  y[t,d] = x[t,d] * softplus((x@W1^T)[t,d] + b1[d]) * s[t]
//              s[t]   = sum_n (x@W2^T+b2)[t,n] * (x@W3^T+b3)[t,n]
// (h0 == 0 kills the exp(dA) term exactly; A unused.)
// T=4096, d=1024, n=16.
// Main GEMM: fp16 inputs (== tf32 precision) + fp32 accum, ldmatrix frags
// with DOUBLE-BUFFERED fragments (hide LDS latency), BK=64, 3-stage cp.async.
// x->fp16 and W1->fp16 conversions fused into s_kernel.
// ============================================================================

#define MAX_T   4096
#define D_MODEL 1024

__device__ float g_s[MAX_T];
__device__ __align__(16) __half g_xh [MAX_T * D_MODEL];
__device__ __align__(16) __half g_w1h[D_MODEL * D_MODEL];

// ---------------------------------------------------------------------------
// helpers
// ---------------------------------------------------------------------------
__device__ __forceinline__ float tf32r(float f) {
    uint32_t r; asm("cvt.rna.tf32.f32 %0, %1;" : "=r"(r) : "f"(f));
    return __uint_as_float(r);
}
// softplus via MUFU (EX2/LG2) fast intrinsics; abs err ~2^-21, fine at 1e-3
__device__ __forceinline__ float softplus_f(float z) {
    return fmaxf(z, 0.0f) + __logf(1.0f + __expf(-fabsf(z)));
}
__device__ __forceinline__ void mma_tf32(float& c0, float& c1, float& c2, float& c3,
                                         float a0, float a1, float a2, float a3,
                                         float b0, float b1) {
    asm volatile(
        "mma.sync.aligned.m16n8k8.row.col.f32.tf32.tf32.f32 "
        "{%0,%1,%2,%3}, {%4,%5,%6,%7}, {%8,%9}, {%0,%1,%2,%3};\n"
        : "+f"(c0), "+f"(c1), "+f"(c2), "+f"(c3)
        : "r"(__float_as_uint(a0)), "r"(__float_as_uint(a1)),
          "r"(__float_as_uint(a2)), "r"(__float_as_uint(a3)),
          "r"(__float_as_uint(b0)), "r"(__float_as_uint(b1)));
}
__device__ __forceinline__ void mma_f16(float& c0, float& c1, float& c2, float& c3,
                                        uint32_t a0, uint32_t a1, uint32_t a2, uint32_t a3,
                                        uint32_t b0, uint32_t b1) {
    asm volatile(
        "mma.sync.aligned.m16n8k16.row.col.f32.f16.f16.f32 "
        "{%0,%1,%2,%3}, {%4,%5,%6,%7}, {%8,%9}, {%0,%1,%2,%3};\n"
        : "+f"(c0), "+f"(c1), "+f"(c2), "+f"(c3)
        : "r"(a0), "r"(a1), "r"(a2), "r"(a3), "r"(b0), "r"(b1));
}
__device__ __forceinline__ void ldsm4(uint32_t* r, uint32_t addr) {
    asm volatile("ldmatrix.sync.aligned.m8n8.x4.shared.b16 {%0,%1,%2,%3}, [%4];"
                 : "=r"(r[0]), "=r"(r[1]), "=r"(r[2]), "=r"(r[3]) : "r"(addr));
}
__device__ __forceinline__ void cp16(uint32_t dst_smem, const void* src) {
    asm volatile("cp.async.cg.shared.global [%0], [%1], 16;"
                 :: "r"(dst_smem), "l"(src));
}
__device__ __forceinline__ void cp_commit() {
    asm volatile("cp.async.commit_group;");
}
template <int N>
__device__ __forceinline__ void cp_wait() {
    asm volatile("cp.async.wait_group %0;" :: "n"(N) : "memory");
}

// ---------------------------------------------------------------------------
// s_kernel: Z2 = X @ [W2;W3]^T (64 tokens/CTA, N=32, K=d), tf32 tensor cores,
// 4-stage cp.async pipeline; s from accumulator layout + shfl.  grid = T/64.
// FUSED: per-slab x tile -> fp16 (x already staged in smem) and a strided
// 1-float4/thread W1 -> fp16 conversion.
// ---------------------------------------------------------------------------
#define SS 4
#define SSTG 12288

__global__ __launch_bounds__(128, 2) void s_kernel(
    const float* __restrict__ x,
    const float* __restrict__ W2, const float* __restrict__ b2,
    const float* __restrict__ W3, const float* __restrict__ b3,
    const float* __restrict__ W1,
    int T, int d)
{
    extern __shared__ float smemf[];
    uint32_t sbase = (uint32_t)__cvta_generic_to_shared(smemf);

    int tid  = threadIdx.x;
    int lane = tid & 31;
    int w    = tid >> 5;
    int gid  = lane >> 2;
    int tig  = lane & 3;
    int t0   = blockIdx.x * 64;

    int lrow = tid >> 3;
    int lc4  = (tid & 7) * 4;
    uint32_t aoff[4], boff[2];
    int aswz[4];
    #pragma unroll
    for (int j = 0; j < 4; j++) {
        int r = lrow + 16 * j;
        aswz[j] = lc4 ^ ((r & 7) << 2);
        aoff[j] = (uint32_t)((r * 32 + aswz[j]) * 4);
    }
    #pragma unroll
    for (int j = 0; j < 2; j++) {
        int r = lrow + 16 * j;
        boff[j] = (uint32_t)((r * 32 + (lc4 ^ ((r & 7) << 2))) * 4);
    }
    const float* xptr  = x  + (size_t)(t0 + lrow) * d + lc4;
    const float* wptr0 = W2 + (size_t)lrow * d + lc4;
    const float* wptr1 = W3 + (size_t)lrow * d + lc4;

    float acc[4][4];
    #pragma unroll
    for (int i = 0; i < 4; i++)
        #pragma unroll
        for (int c = 0; c < 4; c++) acc[i][c] = 0.f;

    const int nslab = d / 32;                       // 32
    const int nthreads_total = (T / 64) * 128;      // 8192
    int gtid = blockIdx.x * 128 + tid;

    #pragma unroll
    for (int j = 0; j < SS - 1; j++) {
        uint32_t sa = sbase + (uint32_t)(j * SSTG);
        uint32_t sb = sa + 8192u;
        int k0 = j * 32;
        #pragma unroll
        for (int qq = 0; qq < 4; qq++)
            cp16(sa + aoff[qq], xptr + (size_t)(16 * qq) * d + k0);
        cp16(sb + boff[0], wptr0 + k0);
        cp16(sb + boff[1], wptr1 + k0);
        cp_commit();
    }

    int xr = gid << 2;

    for (int i = 0; i < nslab; i++) {
        cp_wait<SS - 2>();
        __syncthreads();

        int jn = i + SS - 1;
        if (jn < nslab) {
            uint32_t sa = sbase + (uint32_t)((jn % SS) * SSTG);
            uint32_t sb = sa + 8192u;
            int k0 = jn * 32;
            #pragma unroll
            for (int qq = 0; qq < 4; qq++)
                cp16(sa + aoff[qq], xptr + (size_t)(16 * qq) * d + k0);
            cp16(sb + boff[0], wptr0 + k0);
            cp16(sb + boff[1], wptr1 + k0);
        }
        cp_commit();

        // ---- fused W1 -> fp16: one float4 per thread per slab ----
        {
            int idx = i * nthreads_total + gtid;
            float4 v = ((const float4*)W1)[idx];
            __half2 h0 = __floats2half2_rn(v.x, v.y);
            __half2 h1 = __floats2half2_rn(v.z, v.w);
            uint2 pk;
            pk.x = *(uint32_t*)&h0;
            pk.y = *(uint32_t*)&h1;
            ((uint2*)g_w1h)[idx] = pk;
        }

        const float* As = smemf + (size_t)(i % SS) * (SSTG / 4);
        const float* Bs = As + 2048;

        // ---- fused x -> fp16 conversion of this slab ----
        {
            int k0 = i * 32;
            #pragma unroll
            for (int j = 0; j < 4; j++) {
                int r = lrow + 16 * j;
                float4 v = *(const float4*)(As + r * 32 + aswz[j]);
                __half2 h0 = __floats2half2_rn(v.x, v.y);
                __half2 h1 = __floats2half2_rn(v.z, v.w);
                uint2 pk;
                pk.x = *(uint32_t*)&h0;
                pk.y = *(uint32_t*)&h1;
                *(uint2*)(g_xh + (size_t)(t0 + r) * d + k0 + lc4) = pk;
            }
        }

        #pragma unroll
        for (int kk = 0; kk < 32; kk += 8) {
            int c1 = (kk + tig) ^ xr;
            int c2 = (kk + tig + 4) ^ xr;
            int r = w * 16 + gid;
            float a0 = tf32r(As[r * 32 + c1]);
            float a1 = tf32r(As[(r + 8) * 32 + c1]);
            float a2 = tf32r(As[r * 32 + c2]);
            float a3 = tf32r(As[(r + 8) * 32 + c2]);
            #pragma unroll
            for (int ni = 0; ni < 4; ni++) {
                int n = ni * 8 + gid;
                float b0 = tf32r(Bs[n * 32 + c1]);
                float b1v = tf32r(Bs[n * 32 + c2]);
                mma_tf32(acc[ni][0], acc[ni][1], acc[ni][2], acc[ni][3],
                         a0, a1, a2, a3, b0, b1v);
            }
        }
    }

    int nb0 = tig * 2, nb1 = nb0 + 1, nb2 = nb0 + 8, nb3 = nb0 + 9;
    float p2[4] = {b2[nb0], b2[nb1], b2[nb2], b2[nb3]};
    float p3[4] = {b3[nb0], b3[nb1], b3[nb2], b3[nb3]};

    #pragma unroll
    for (int h = 0; h < 2; h++) {
        float p =
            (acc[0][h*2+0] + p2[0]) * (acc[2][h*2+0] + p3[0]) +
            (acc[0][h*2+1] + p2[1]) * (acc[2][h*2+1] + p3[1]) +
            (acc[1][h*2+0] + p2[2]) * (acc[3][h*2+0] + p3[2]) +
            (acc[1][h*2+1] + p2[3]) * (acc[3][h*2+1] + p3[3]);
        p += __shfl_xor_sync(0xffffffffu, p, 1);
        p += __shfl_xor_sync(0xffffffffu, p, 2);
        if (tig == 0) {
            int t = t0 + w * 16 + gid + h * 8;
            if (t < T) g_s[t] = p;
        }
    }
}

// ---------------------------------------------------------------------------
// main_kernel: Z = X @ W1^T (fp16 in, fp32 accum), y = x*softplus(Z+b1)*s.
// BM=BN=128, BK=64 halves. 128 threads = 4 warps (2x2), warp tile 64x64.
// Chunk swizzle p = c ^ (r&7).  3-stage pipeline, 2 CTAs/SM.
// Fragments DOUBLE-BUFFERED: ldsm for k-step kk+1 issued before mma of kk.
// ---------------------------------------------------------------------------
#define MS   3
#define MSTG 32768                 // bytes/stage: A 16KB + B 16KB

__global__ __launch_bounds__(128, 2) void main_kernel(
    const float* __restrict__ x, const float* __restrict__ b1,
    float* __restrict__ y, int T, int d)
{
    extern __shared__ char smem[];
    uint32_t sbase = (uint32_t)__cvta_generic_to_shared(smem);

    int tid  = threadIdx.x;
    int lane = tid & 31;
    int warp = tid >> 5;
    int wm   = warp >> 1;        // 0..1
    int wn   = warp & 1;         // 0..1
    int gid  = lane >> 2;        // 0..7
    int tig  = lane & 3;         // 0..3

    int bm = blockIdx.x * 128;
    int bn = blockIdx.y * 128;

    // ---- gmem->smem map: chunk q = tid&7, row = (tid>>3) + 16*j ----
    int q    = tid & 7;
    int rowb = tid >> 3;           // 0..15
    uint32_t soff[8];
    #pragma unroll
    for (int j = 0; j < 8; j++) {
        int r = rowb + 16 * j;
        soff[j] = (uint32_t)(r * 128 + ((q ^ (r & 7)) << 4));
    }
    const __half* aptr = g_xh  + (size_t)(bm + rowb) * d + q * 8;
    const __half* bptr = g_w1h + (size_t)(bn + rowb) * d + q * 8;

    // ---- ldmatrix lane geometry ----
    int g = lane >> 3, lrow8 = lane & 7;
    uint32_t abase[4]; int axor[4];
    #pragma unroll
    for (int mi = 0; mi < 4; mi++) {
        int r = wm * 64 + mi * 16 + (g & 1) * 8 + lrow8;
        abase[mi] = (uint32_t)(r * 128);
        axor[mi]  = r & 7;
    }
    int acb = g >> 1;
    uint32_t bbase[4]; int bxor[4];
    #pragma unroll
    for (int nb = 0; nb < 4; nb++) {
        int r = wn * 64 + nb * 16 + (g >> 1) * 8 + lrow8;
        bbase[nb] = (uint32_t)(r * 128);
        bxor[nb]  = r & 7;
    }
    int bcb = g & 1;

    float acc[4][8][4];
    #pragma unroll
    for (int mi = 0; mi < 4; mi++)
        #pragma unroll
        for (int nj = 0; nj < 8; nj++)
            #pragma unroll
            for (int c = 0; c < 4; c++) acc[mi][nj][c] = 0.f;

    const int nslab = d / 64;      // 16

    // ---- prologue: stages 0..MS-2 ----
    #pragma unroll
    for (int j = 0; j < MS - 1; j++) {
        uint32_t sa = sbase + (uint32_t)(j * MSTG);
        uint32_t sb = sa + 16384u;
        int k0 = j * 64;
        #pragma unroll
        for (int jj = 0; jj < 8; jj++) {
            cp16(sa + soff[jj], aptr + (size_t)(16 * jj) * d + k0);
            cp16(sb + soff[jj], bptr + (size_t)(16 * jj) * d + k0);
        }
        cp_commit();
    }

    for (int i = 0; i < nslab; i++) {
        cp_wait<MS - 2>();
        __syncthreads();

        int jn = i + MS - 1;
        if (jn < nslab) {
            uint32_t sa = sbase + (uint32_t)((jn % MS) * MSTG);
            uint32_t sb = sa + 16384u;
            int k0 = jn * 64;
            #pragma unroll
            for (int jj = 0; jj < 8; jj++) {
                cp16(sa + soff[jj], aptr + (size_t)(16 * jj) * d + k0);
                cp16(sb + soff[jj], bptr + (size_t)(16 * jj) * d + k0);
            }
        }
        cp_commit();

        uint32_t sA = sbase + (uint32_t)((i % MS) * MSTG);
        uint32_t sB = sA + 16384u;

        // fragment double buffers
        uint32_t abuf[2][4][4], bbuf[2][4][4];

        // preload k-step 0
        #pragma unroll
        for (int mi = 0; mi < 4; mi++)
            ldsm4(abuf[0][mi], sA + abase[mi] + (uint32_t)(((0 + acb) ^ axor[mi]) << 4));
        #pragma unroll
        for (int nb = 0; nb < 4; nb++)
            ldsm4(bbuf[0][nb], sB + bbase[nb] + (uint32_t)(((0 + bcb) ^ bxor[nb]) << 4));

        #pragma unroll
        for (int kk = 0; kk < 4; kk++) {
            int cur = kk & 1, nxt = cur ^ 1;
            if (kk < 3) {
                int c2 = (kk + 1) * 2;
                #pragma unroll
                for (int mi = 0; mi < 4; mi++)
                    ldsm4(abuf[nxt][mi], sA + abase[mi] + (uint32_t)((((c2 + acb) ^ axor[mi])) << 4));
                #pragma unroll
                for (int nb = 0; nb < 4; nb++)
                    ldsm4(bbuf[nxt][nb], sB + bbase[nb] + (uint32_t)((((c2 + bcb) ^ bxor[nb])) << 4));
            }
            #pragma unroll
            for (int mi = 0; mi < 4; mi++)
                #pragma unroll
                for (int nj = 0; nj < 8; nj++)
                    mma_f16(acc[mi][nj][0], acc[mi][nj][1],
                            acc[mi][nj][2], acc[mi][nj][3],
                            abuf[cur][mi][0], abuf[cur][mi][1],
                            abuf[cur][mi][2], abuf[cur][mi][3],
                            bbuf[cur][nj >> 1][(nj & 1) * 2],
                            bbuf[cur][nj >> 1][(nj & 1) * 2 + 1]);
        }
    }

    // ---- fused epilogue: y = x * softplus(z + b1) * s ----
    #pragma unroll
    for (int mi = 0; mi < 4; mi++) {
        int r0 = bm + wm * 64 + mi * 16 + gid;
        int r1 = r0 + 8;
        float sv0 = g_s[r0];
        float sv1 = g_s[r1];
        #pragma unroll
        for (int nj = 0; nj < 8; nj++) {
            int c0 = bn + wn * 64 + nj * 8 + tig * 2;
            float2 bias = *(const float2*)&b1[c0];
            float2 x0 = *(const float2*)&x[(size_t)r0 * d + c0];
            float2 x1 = *(const float2*)&x[(size_t)r1 * d + c0];
            float2 o0, o1;
            o0.x = x0.x * softplus_f(acc[mi][nj][0] + bias.x) * sv0;
            o0.y = x0.y * softplus_f(acc[mi][nj][1] + bias.y) * sv0;
            o1.x = x1.x * softplus_f(acc[mi][nj][2] + bias.x) * sv1;
            o1.y = x1.y * softplus_f(acc[mi][nj][3] + bias.y) * sv1;
            *(float2*)&y[(size_t)r0 * d + c0] = o0;
            *(float2*)&y[(size_t)r1 * d + c0] = o1;
        }
    }
}

// ---------------------------------------------------------------------------
// launch — inputs (metadata order): x, W1, b1, W2, b2, W3, b3, A
// ---------------------------------------------------------------------------
extern "C" void kernel_launch(void* const* d_in, const int* in_sizes, int n_in,
                              void* d_out, int out_size)
{
    const float* x  = (const float*)d_in[0];
    const float* W1 = (const float*)d_in[1];
    const float* b1 = (const float*)d_in[2];
    const float* W2 = (const float*)d_in[3];
    const float* b2 = (const float*)d_in[4];
    const float* W3 = (const float*)d_in[5];
    const float* b3 = (const float*)d_in[6];
    // d_in[7] = A: unused (h0 == 0 kills exp(dA)*h0 exactly)

    int d = in_sizes[2];          // d_model (1024)
    int T = in_sizes[0] / d;      // tokens (4096)
    float* y = (float*)d_out;

    const int SMEM_MAIN = MS * MSTG;   // 3 * 32KB = 96KB
    const int SMEM_S    = SS * SSTG;   // 4 * 12KB = 48KB

    cudaFuncSetAttribute(main_kernel, cudaFuncAttributeMaxDynamicSharedMemorySize, SMEM_MAIN);
    cudaFuncSetAttribute(s_kernel,    cudaFuncAttributeMaxDynamicSharedMemorySize, SMEM_S);

    s_kernel<<<T / 64, 128, SMEM_S>>>(x, W2, b2, W3, b3, W1, T, d);
    dim3 grid(T / 128, d / 128);
    main_kernel<<<grid, 128, SMEM_MAIN>>>(x, b1, y, T, d);
}

// round 15
// speedup vs baseline: 4.2648x; 1.1048x over previous
#include <cuda_runtime.h>
#include <cuda_fp16.h>
#include <cstdint>
#include <cstddef>

// ============================================================================
// S6 reduced:  y[t,d] = x[t,d] * softplus((x@W1^T)[t,d] + b1[d]) * s[t]
//              s[t]   = sum_n (x@W2^T+b2)[t,n] * (x@W3^T+b3)[t,n]
// (h0 == 0 kills the exp(dA) term exactly; A unused.)
// T=4096, d=1024, n=16.
// Main: fp16 mma (== tf32 precision) + fp32 accum, double-buffered ldmatrix,
//       BK=64, 3-stage cp.async with loads interleaved into the mma loop.
// s:    128 CTAs, 32 tokens/CTA, warp K-split (2 token-groups x 2 K-halves),
//       smem reduction; x->fp16 and W1->fp16 conversions fused in.
// ============================================================================

#define MAX_T   4096
#define D_MODEL 1024

__device__ float g_s[MAX_T];
__device__ __align__(16) __half g_xh [MAX_T * D_MODEL];
__device__ __align__(16) __half g_w1h[D_MODEL * D_MODEL];

// ---------------------------------------------------------------------------
// helpers
// ---------------------------------------------------------------------------
__device__ __forceinline__ float tf32r(float f) {
    uint32_t r; asm("cvt.rna.tf32.f32 %0, %1;" : "=r"(r) : "f"(f));
    return __uint_as_float(r);
}
__device__ __forceinline__ float softplus_f(float z) {
    return fmaxf(z, 0.0f) + __logf(1.0f + __expf(-fabsf(z)));
}
__device__ __forceinline__ void mma_tf32(float& c0, float& c1, float& c2, float& c3,
                                         float a0, float a1, float a2, float a3,
                                         float b0, float b1) {
    asm volatile(
        "mma.sync.aligned.m16n8k8.row.col.f32.tf32.tf32.f32 "
        "{%0,%1,%2,%3}, {%4,%5,%6,%7}, {%8,%9}, {%0,%1,%2,%3};\n"
        : "+f"(c0), "+f"(c1), "+f"(c2), "+f"(c3)
        : "r"(__float_as_uint(a0)), "r"(__float_as_uint(a1)),
          "r"(__float_as_uint(a2)), "r"(__float_as_uint(a3)),
          "r"(__float_as_uint(b0)), "r"(__float_as_uint(b1)));
}
__device__ __forceinline__ void mma_f16(float& c0, float& c1, float& c2, float& c3,
                                        uint32_t a0, uint32_t a1, uint32_t a2, uint32_t a3,
                                        uint32_t b0, uint32_t b1) {
    asm volatile(
        "mma.sync.aligned.m16n8k16.row.col.f32.f16.f16.f32 "
        "{%0,%1,%2,%3}, {%4,%5,%6,%7}, {%8,%9}, {%0,%1,%2,%3};\n"
        : "+f"(c0), "+f"(c1), "+f"(c2), "+f"(c3)
        : "r"(a0), "r"(a1), "r"(a2), "r"(a3), "r"(b0), "r"(b1));
}
__device__ __forceinline__ void ldsm4(uint32_t* r, uint32_t addr) {
    asm volatile("ldmatrix.sync.aligned.m8n8.x4.shared.b16 {%0,%1,%2,%3}, [%4];"
                 : "=r"(r[0]), "=r"(r[1]), "=r"(r[2]), "=r"(r[3]) : "r"(addr));
}
__device__ __forceinline__ void cp16(uint32_t dst_smem, const void* src) {
    asm volatile("cp.async.cg.shared.global [%0], [%1], 16;"
                 :: "r"(dst_smem), "l"(src));
}
__device__ __forceinline__ void cp_commit() {
    asm volatile("cp.async.commit_group;");
}
template <int N>
__device__ __forceinline__ void cp_wait() {
    asm volatile("cp.async.wait_group %0;" :: "n"(N) : "memory");
}

// ---------------------------------------------------------------------------
// s_kernel v2: Z2 = X @ [W2;W3]^T, 32 tokens/CTA, grid = T/32 = 128 CTAs.
// 4 warps: tg = warp&1 (16-token group), kh = warp>>1 (K half of 512).
// Each warp: 16 tokens x 32 N over K/2, 16 slabs of 32.  Partial accs
// reduced across K-halves via smem, then s via pair-product + shfl.
// Stage: A 2x(32x32 f32) 8KB + W 2x(32x32 f32) 8KB = 16KB, 4 stages.
// FUSED: x->fp16 (from staged tiles) and W1->fp16 (1 float4/thread/slab).
// ---------------------------------------------------------------------------
#define SS   4
#define SSTG 16384

__global__ __launch_bounds__(128, 2) void s_kernel(
    const float* __restrict__ x,
    const float* __restrict__ W2, const float* __restrict__ b2,
    const float* __restrict__ W3, const float* __restrict__ b3,
    const float* __restrict__ W1,
    int T, int d)
{
    extern __shared__ float smemf[];
    uint32_t sbase = (uint32_t)__cvta_generic_to_shared(smemf);

    int tid  = threadIdx.x;
    int lane = tid & 31;
    int w    = tid >> 5;
    int tg   = w & 1;            // token group: rows tg*16 .. tg*16+15
    int kh   = w >> 1;           // K half: k in [kh*512, kh*512+512)
    int gid  = lane >> 2;
    int tig  = lane & 3;
    int t0   = blockIdx.x * 32;

    // ---- load geometry: 4 A float4 + 4 W float4 per thread per slab ----
    int  ahalf[4], arow[4], ac4[4];
    uint32_t aoff[4], woff[4];
    const float* asrc[4];
    const float* wsrc[4];
    #pragma unroll
    for (int j = 0; j < 4; j++) {
        int id   = tid + 128 * j;            // 0..511
        ahalf[j] = id >> 8;
        arow[j]  = (id >> 3) & 31;
        ac4[j]   = (id & 7) * 4;
        int sw   = ac4[j] ^ ((arow[j] & 7) << 2);
        aoff[j]  = (uint32_t)((ahalf[j] * 1024 + arow[j] * 32 + sw) * 4);
        woff[j]  = aoff[j] + 8192u;          // W region after 8KB of A
        asrc[j]  = x + (size_t)(t0 + arow[j]) * d + ahalf[j] * 512 + ac4[j];
        const float* wr = (arow[j] < 16) ? (W2 + (size_t)arow[j] * d)
                                         : (W3 + (size_t)(arow[j] - 16) * d);
        wsrc[j]  = wr + ahalf[j] * 512 + ac4[j];
    }

    float acc[4][4];
    #pragma unroll
    for (int i = 0; i < 4; i++)
        #pragma unroll
        for (int c = 0; c < 4; c++) acc[i][c] = 0.f;

    const int nslab = d / 64;                 // 16 (each half advances 32/slab)
    const int nthreads_total = (T / 32) * 128; // 16384
    int gtid = blockIdx.x * 128 + tid;

    // ---- prologue: stages 0..SS-2 ----
    #pragma unroll
    for (int j = 0; j < SS - 1; j++) {
        uint32_t sa = sbase + (uint32_t)(j * SSTG);
        int k0 = j * 32;
        #pragma unroll
        for (int q = 0; q < 4; q++) {
            cp16(sa + aoff[q], asrc[q] + k0);
            cp16(sa + woff[q], wsrc[q] + k0);
        }
        cp_commit();
    }

    int xr = gid << 2;

    for (int i = 0; i < nslab; i++) {
        cp_wait<SS - 2>();
        __syncthreads();

        int jn = i + SS - 1;
        if (jn < nslab) {
            uint32_t sa = sbase + (uint32_t)((jn % SS) * SSTG);
            int k0 = jn * 32;
            #pragma unroll
            for (int q = 0; q < 4; q++) {
                cp16(sa + aoff[q], asrc[q] + k0);
                cp16(sa + woff[q], wsrc[q] + k0);
            }
        }
        cp_commit();

        // ---- fused W1 -> fp16: one float4 per thread per slab ----
        {
            int idx = i * nthreads_total + gtid;   // covers d*d/4 = 262144
            float4 v = ((const float4*)W1)[idx];
            __half2 h0 = __floats2half2_rn(v.x, v.y);
            __half2 h1 = __floats2half2_rn(v.z, v.w);
            uint2 pk;
            pk.x = *(uint32_t*)&h0;
            pk.y = *(uint32_t*)&h1;
            ((uint2*)g_w1h)[idx] = pk;
        }

        const float* St = smemf + (size_t)(i % SS) * (SSTG / 4);
        int k0 = i * 32;

        // ---- fused x -> fp16 conversion of this slab's staged tiles ----
        #pragma unroll
        for (int j = 0; j < 4; j++) {
            float4 v = *(const float4*)((const char*)St + aoff[j]);
            __half2 h0 = __floats2half2_rn(v.x, v.y);
            __half2 h1 = __floats2half2_rn(v.z, v.w);
            uint2 pk;
            pk.x = *(uint32_t*)&h0;
            pk.y = *(uint32_t*)&h1;
            *(uint2*)(g_xh + (size_t)(t0 + arow[j]) * d
                      + ahalf[j] * 512 + k0 + ac4[j]) = pk;
        }

        const float* As = St + kh * 1024;          // this warp's A half block
        const float* Bs = St + 2048 + kh * 1024;   // this warp's W half block

        #pragma unroll
        for (int kk = 0; kk < 32; kk += 8) {
            int c1 = (kk + tig) ^ xr;
            int c2 = (kk + tig + 4) ^ xr;
            int r = tg * 16 + gid;
            float a0 = tf32r(As[r * 32 + c1]);
            float a1 = tf32r(As[(r + 8) * 32 + c1]);
            float a2 = tf32r(As[r * 32 + c2]);
            float a3 = tf32r(As[(r + 8) * 32 + c2]);
            #pragma unroll
            for (int ni = 0; ni < 4; ni++) {
                int n = ni * 8 + gid;
                float b0 = tf32r(Bs[n * 32 + c1]);
                float b1v = tf32r(Bs[n * 32 + c2]);
                mma_tf32(acc[ni][0], acc[ni][1], acc[ni][2], acc[ni][3],
                         a0, a1, a2, a3, b0, b1v);
            }
        }
    }

    // ---- reduce K-halves via smem (reuse stage 0; all cp.async drained) ----
    cp_wait<0>();
    __syncthreads();
    float* sred = smemf;    // 2 tg x 16 vals x 32 lanes = 4KB
    if (kh == 1) {
        #pragma unroll
        for (int ni = 0; ni < 4; ni++)
            #pragma unroll
            for (int c = 0; c < 4; c++)
                sred[tg * 512 + (ni * 4 + c) * 32 + lane] = acc[ni][c];
    }
    __syncthreads();
    if (kh == 0) {
        #pragma unroll
        for (int ni = 0; ni < 4; ni++)
            #pragma unroll
            for (int c = 0; c < 4; c++)
                acc[ni][c] += sred[tg * 512 + (ni * 4 + c) * 32 + lane];

        // s = sum_n (Z[:,n]+b2[n]) * (Z[:,n+16]+b3[n])
        int nb0 = tig * 2, nb1 = nb0 + 1, nb2 = nb0 + 8, nb3 = nb0 + 9;
        float p2[4] = {b2[nb0], b2[nb1], b2[nb2], b2[nb3]};
        float p3[4] = {b3[nb0], b3[nb1], b3[nb2], b3[nb3]};

        #pragma unroll
        for (int h = 0; h < 2; h++) {
            float p =
                (acc[0][h*2+0] + p2[0]) * (acc[2][h*2+0] + p3[0]) +
                (acc[0][h*2+1] + p2[1]) * (acc[2][h*2+1] + p3[1]) +
                (acc[1][h*2+0] + p2[2]) * (acc[3][h*2+0] + p3[2]) +
                (acc[1][h*2+1] + p2[3]) * (acc[3][h*2+1] + p3[3]);
            p += __shfl_xor_sync(0xffffffffu, p, 1);
            p += __shfl_xor_sync(0xffffffffu, p, 2);
            if (tig == 0) {
                int t = t0 + tg * 16 + gid + h * 8;
                if (t < T) g_s[t] = p;
            }
        }
    }
}

// ---------------------------------------------------------------------------
// main_kernel: Z = X @ W1^T (fp16 in, fp32 accum), y = x*softplus(Z+b1)*s.
// BM=BN=128, BK=64. 4 warps (2x2), warp tile 64x64, swizzle p = c ^ (r&7).
// 3-stage pipeline, 2 CTAs/SM.  Fragments double-buffered; the 16 cp.async
// of the next slab are interleaved 4-per-k-step into the mma loop.
// ---------------------------------------------------------------------------
#define MS   3
#define MSTG 32768

__global__ __launch_bounds__(128, 2) void main_kernel(
    const float* __restrict__ x, const float* __restrict__ b1,
    float* __restrict__ y, int T, int d)
{
    extern __shared__ char smem[];
    uint32_t sbase = (uint32_t)__cvta_generic_to_shared(smem);

    int tid  = threadIdx.x;
    int lane = tid & 31;
    int warp = tid >> 5;
    int wm   = warp >> 1;
    int wn   = warp & 1;
    int gid  = lane >> 2;
    int tig  = lane & 3;

    int bm = blockIdx.x * 128;
    int bn = blockIdx.y * 128;

    int q    = tid & 7;
    int rowb = tid >> 3;
    uint32_t soff[8];
    #pragma unroll
    for (int j = 0; j < 8; j++) {
        int r = rowb + 16 * j;
        soff[j] = (uint32_t)(r * 128 + ((q ^ (r & 7)) << 4));
    }
    const __half* aptr = g_xh  + (size_t)(bm + rowb) * d + q * 8;
    const __half* bptr = g_w1h + (size_t)(bn + rowb) * d + q * 8;

    int g = lane >> 3, lrow8 = lane & 7;
    uint32_t abase[4]; int axor[4];
    #pragma unroll
    for (int mi = 0; mi < 4; mi++) {
        int r = wm * 64 + mi * 16 + (g & 1) * 8 + lrow8;
        abase[mi] = (uint32_t)(r * 128);
        axor[mi]  = r & 7;
    }
    int acb = g >> 1;
    uint32_t bbase[4]; int bxor[4];
    #pragma unroll
    for (int nb = 0; nb < 4; nb++) {
        int r = wn * 64 + nb * 16 + (g >> 1) * 8 + lrow8;
        bbase[nb] = (uint32_t)(r * 128);
        bxor[nb]  = r & 7;
    }
    int bcb = g & 1;

    float acc[4][8][4];
    #pragma unroll
    for (int mi = 0; mi < 4; mi++)
        #pragma unroll
        for (int nj = 0; nj < 8; nj++)
            #pragma unroll
            for (int c = 0; c < 4; c++) acc[mi][nj][c] = 0.f;

    const int nslab = d / 64;      // 16

    #pragma unroll
    for (int j = 0; j < MS - 1; j++) {
        uint32_t sa = sbase + (uint32_t)(j * MSTG);
        uint32_t sb = sa + 16384u;
        int k0 = j * 64;
        #pragma unroll
        for (int jj = 0; jj < 8; jj++) {
            cp16(sa + soff[jj], aptr + (size_t)(16 * jj) * d + k0);
            cp16(sb + soff[jj], bptr + (size_t)(16 * jj) * d + k0);
        }
        cp_commit();
    }

    for (int i = 0; i < nslab; i++) {
        cp_wait<MS - 2>();
        __syncthreads();

        int jn = i + MS - 1;
        bool doload = jn < nslab;
        uint32_t nsa = 0, nsb = 0; int nk0 = 0;
        if (doload) {
            nsa = sbase + (uint32_t)((jn % MS) * MSTG);
            nsb = nsa + 16384u;
            nk0 = jn * 64;
        }

        uint32_t sA = sbase + (uint32_t)((i % MS) * MSTG);
        uint32_t sB = sA + 16384u;

        uint32_t abuf[2][4][4], bbuf[2][4][4];
        #pragma unroll
        for (int mi = 0; mi < 4; mi++)
            ldsm4(abuf[0][mi], sA + abase[mi] + (uint32_t)(((acb) ^ axor[mi]) << 4));
        #pragma unroll
        for (int nb = 0; nb < 4; nb++)
            ldsm4(bbuf[0][nb], sB + bbase[nb] + (uint32_t)(((bcb) ^ bxor[nb]) << 4));

        #pragma unroll
        for (int kk = 0; kk < 4; kk++) {
            int cur = kk & 1, nxt = cur ^ 1;
            if (kk < 3) {
                int c2 = (kk + 1) * 2;
                #pragma unroll
                for (int mi = 0; mi < 4; mi++)
                    ldsm4(abuf[nxt][mi], sA + abase[mi] + (uint32_t)((((c2 + acb) ^ axor[mi])) << 4));
                #pragma unroll
                for (int nb = 0; nb < 4; nb++)
                    ldsm4(bbuf[nxt][nb], sB + bbase[nb] + (uint32_t)((((c2 + bcb) ^ bxor[nb])) << 4));
            }
            // interleave 4 of next slab's 16 cp.async per k-step
            if (doload) {
                int j0 = kk * 2;
                cp16(nsa + soff[j0],     aptr + (size_t)(16 * j0) * d + nk0);
                cp16(nsa + soff[j0 + 1], aptr + (size_t)(16 * (j0 + 1)) * d + nk0);
                cp16(nsb + soff[j0],     bptr + (size_t)(16 * j0) * d + nk0);
                cp16(nsb + soff[j0 + 1], bptr + (size_t)(16 * (j0 + 1)) * d + nk0);
            }
            #pragma unroll
            for (int mi = 0; mi < 4; mi++)
                #pragma unroll
                for (int nj = 0; nj < 8; nj++)
                    mma_f16(acc[mi][nj][0], acc[mi][nj][1],
                            acc[mi][nj][2], acc[mi][nj][3],
                            abuf[cur][mi][0], abuf[cur][mi][1],
                            abuf[cur][mi][2], abuf[cur][mi][3],
                            bbuf[cur][nj >> 1][(nj & 1) * 2],
                            bbuf[cur][nj >> 1][(nj & 1) * 2 + 1]);
        }
        cp_commit();
    }

    // ---- fused epilogue: y = x * softplus(z + b1) * s ----
    #pragma unroll
    for (int mi = 0; mi < 4; mi++) {
        int r0 = bm + wm * 64 + mi * 16 + gid;
        int r1 = r0 + 8;
        float sv0 = g_s[r0];
        float sv1 = g_s[r1];
        #pragma unroll
        for (int nj = 0; nj < 8; nj++) {
            int c0 = bn + wn * 64 + nj * 8 + tig * 2;
            float2 bias = *(const float2*)&b1[c0];
            float2 x0 = *(const float2*)&x[(size_t)r0 * d + c0];
            float2 x1 = *(const float2*)&x[(size_t)r1 * d + c0];
            float2 o0, o1;
            o0.x = x0.x * softplus_f(acc[mi][nj][0] + bias.x) * sv0;
            o0.y = x0.y * softplus_f(acc[mi][nj][1] + bias.y) * sv0;
            o1.x = x1.x * softplus_f(acc[mi][nj][2] + bias.x) * sv1;
            o1.y = x1.y * softplus_f(acc[mi][nj][3] + bias.y) * sv1;
            *(float2*)&y[(size_t)r0 * d + c0] = o0;
            *(float2*)&y[(size_t)r1 * d + c0] = o1;
        }
    }
}

// ---------------------------------------------------------------------------
// launch — inputs (metadata order): x, W1, b1, W2, b2, W3, b3, A
// ---------------------------------------------------------------------------
extern "C" void kernel_launch(void* const* d_in, const int* in_sizes, int n_in,
                              void* d_out, int out_size)
{
    const float* x  = (const float*)d_in[0];
    const float* W1 = (const float*)d_in[1];
    const float* b1 = (const float*)d_in[2];
    const float* W2 = (const float*)d_in[3];
    const float* b2 = (const float*)d_in[4];
    const float* W3 = (const float*)d_in[5];
    const float* b3 = (const float*)d_in[6];
    // d_in[7] = A: unused (h0 == 0 kills exp(dA)*h0 exactly)

    int d = in_sizes[2];          // d_model (1024)
    int T = in_sizes[0] / d;      // tokens (4096)
    float* y = (float*)d_out;

    const int SMEM_MAIN = MS * MSTG;   // 3 * 32KB = 96KB
    const int SMEM_S    = SS * SSTG;   // 4 * 16KB = 64KB

    cudaFuncSetAttribute(main_kernel, cudaFuncAttributeMaxDynamicSharedMemorySize, SMEM_MAIN);
    cudaFuncSetAttribute(s_kernel,    cudaFuncAttributeMaxDynamicSharedMemorySize, SMEM_S);

    s_kernel<<<T / 32, 128, SMEM_S>>>(x, W2, b2, W3, b3, W1, T, d);
    dim3 grid(T / 128, d / 128);
    main_kernel<<<grid, 128, SMEM_MAIN>>>(x, b1, y, T, d);
}